// round 13
// baseline (speedup 1.0000x reference)
#include <cuda_runtime.h>
#include <cuda_fp16.h>
#include <cstdint>

// Problem constants
#define Bn   4
#define Vn   6
#define Cn   256
#define HWn  1024
#define Sn   6144
#define WIN  3
#define QSCALE (0.125f * 1.44269504f)   // 1/sqrt(64) * log2(e)

// Scratch (__device__ globals; allocation-free rule)
__device__ __half g_xt [(size_t)Bn * Vn * HWn * Cn];  // [bv][hw][c]
__device__ __half g_qh [(size_t)Bn * Sn  * Cn];       // [B,S,C]  (scaled by QSCALE)
__device__ __half g_kh [(size_t)Bn * HWn * Cn];       // [B,HW,C]
__device__ __half g_vt [(size_t)Bn * Cn  * HWn];      // [B,C,HW] (transposed)
__device__ __half g_aoh[(size_t)Bn * Sn  * Cn];       // [B,S,C]
__device__ __half g_wqt[256 * 256];                   // W^T [n][k]
__device__ __half g_wkt[256 * 1536];
__device__ __half g_wvt[256 * 1536];
__device__ __half g_wot[256 * 256];

// ---------------------------------------------------------------------------
// helpers
// ---------------------------------------------------------------------------
__device__ __forceinline__ void mma_f16(float* d, const uint32_t* a,
                                        uint32_t b0, uint32_t b1)
{
    asm volatile(
        "mma.sync.aligned.m16n8k16.row.col.f32.f16.f16.f32 "
        "{%0,%1,%2,%3}, {%4,%5,%6,%7}, {%8,%9}, {%0,%1,%2,%3};"
        : "+f"(d[0]), "+f"(d[1]), "+f"(d[2]), "+f"(d[3])
        : "r"(a[0]), "r"(a[1]), "r"(a[2]), "r"(a[3]), "r"(b0), "r"(b1));
}

// fp16-accumulator mma: D,C are 2 regs (4 halves). 2x tensor throughput.
__device__ __forceinline__ void mma_f16h(uint32_t& d0, uint32_t& d1,
                                         const uint32_t* a,
                                         uint32_t b0, uint32_t b1)
{
    asm volatile(
        "mma.sync.aligned.m16n8k16.row.col.f16.f16.f16.f16 "
        "{%0,%1}, {%2,%3,%4,%5}, {%6,%7}, {%0,%1};"
        : "+r"(d0), "+r"(d1)
        : "r"(a[0]), "r"(a[1]), "r"(a[2]), "r"(a[3]), "r"(b0), "r"(b1));
}

__device__ __forceinline__ uint32_t h2exp2u(uint32_t x)
{
    __half2 h = h2exp2(*reinterpret_cast<__half2*>(&x));
    return *reinterpret_cast<uint32_t*>(&h);
}

__device__ __forceinline__ __half2 u2h2(uint32_t x)
{
    return *reinterpret_cast<__half2*>(&x);
}

__device__ __forceinline__ void cpa16(__half* dst, const __half* src)
{
    uint32_t s = (uint32_t)__cvta_generic_to_shared(dst);
    asm volatile("cp.async.cg.shared.global [%0], [%1], 16;" :: "r"(s), "l"(src));
}
#define CP_COMMIT() asm volatile("cp.async.commit_group;")
#define CP_WAIT1()  asm volatile("cp.async.wait_group 1;")

#define ASTR 40     // halves per A smem row (32 k + 8 pad)
#define BSTR 40
#define KVS  72     // halves per KV smem row (64 + 8 pad)
#define HNINF 0xFC00u   // fp16 -inf bits

// ---------------------------------------------------------------------------
// prep: transpose x -> fp16 [bv][hw][c]
// ---------------------------------------------------------------------------
__global__ void prep_x(const float* __restrict__ x)
{
    __shared__ float ts[32][33];
    const int hw0 = blockIdx.x * 32, c0 = blockIdx.y * 32, bv = blockIdx.z;
    const int tx = threadIdx.x, ty = threadIdx.y;
    #pragma unroll
    for (int r = 0; r < 4; r++) {
        const int c = c0 + ty * 4 + r;
        ts[ty * 4 + r][tx] = x[((size_t)bv * 256 + c) * 1024 + hw0 + tx];
    }
    __syncthreads();
    #pragma unroll
    for (int r = 0; r < 4; r++) {
        const int hw = hw0 + ty * 4 + r;
        g_xt[((size_t)bv * 1024 + hw) * 256 + c0 + tx] = __float2half(ts[tx][ty * 4 + r]);
    }
}

// prep: weights W [K][256] -> W^T fp16 [256][K]
__global__ void prep_w(const float* __restrict__ Wq, const float* __restrict__ Wk,
                       const float* __restrict__ Wv, const float* __restrict__ Wo)
{
    const float* src; __half* dst; int K;
    switch (blockIdx.z) {
        case 0:  src = Wq; dst = g_wqt; K = 256;  break;
        case 1:  src = Wk; dst = g_wkt; K = 1536; break;
        case 2:  src = Wv; dst = g_wvt; K = 1536; break;
        default: src = Wo; dst = g_wot; K = 256;  break;
    }
    const int k0 = blockIdx.y * 32;
    if (k0 >= K) return;
    const int n0 = blockIdx.x * 32;
    const int tx = threadIdx.x, ty = threadIdx.y;
    __shared__ float ts[32][33];
    #pragma unroll
    for (int r = 0; r < 4; r++)
        ts[ty * 4 + r][tx] = src[(size_t)(k0 + ty * 4 + r) * 256 + n0 + tx];
    __syncthreads();
    #pragma unroll
    for (int r = 0; r < 4; r++)
        dst[(size_t)(n0 + ty * 4 + r) * K + k0 + tx] = __float2half(ts[tx][ty * 4 + r]);
}

// ---------------------------------------------------------------------------
// Fused Q + KV projection launch (unchanged).
// ---------------------------------------------------------------------------
__device__ __forceinline__ void qproj_body(__half* sbuf, int bx, int by,
                                           const float* __restrict__ bq)
{
    __half* As = sbuf;
    __half* Bs = sbuf + 2 * 128 * ASTR;
    const int tid = threadIdx.x;
    const int w = tid >> 5, lane = tid & 31, g = lane >> 2, t = lane & 3;
    const int wm = w >> 1, wn = w & 1;
    const int m0 = by * 128, n0 = bx * 64;
    const __half* Ag = g_xt + (size_t)m0 * 256;
    const __half* Bg = g_wqt + (size_t)n0 * 256;

    const int ar0 = tid >> 2,           ac0 = (tid & 3) * 8;
    const int ar1 = (tid + 256) >> 2,   ac1 = ac0;
    const int br  = tid >> 2,           bc  = (tid & 3) * 8;

    #pragma unroll
    for (int pc = 0; pc < 2; pc++) {
        __half* Asb = As + pc * 128 * ASTR;
        __half* Bsb = Bs + pc * 64 * BSTR;
        cpa16(&Asb[ar0 * ASTR + ac0], Ag + (size_t)ar0 * 256 + pc * 32 + ac0);
        cpa16(&Asb[ar1 * ASTR + ac1], Ag + (size_t)ar1 * 256 + pc * 32 + ac1);
        cpa16(&Bsb[br * BSTR + bc],   Bg + (size_t)br * 256 + pc * 32 + bc);
        CP_COMMIT();
    }

    float acc[2][4][4] = {};
    for (int kc = 0; kc < 8; kc++) {
        CP_WAIT1();
        __syncthreads();
        const __half* Ab = As + (kc & 1) * 128 * ASTR;
        const __half* Bb = Bs + (kc & 1) * 64 * BSTR;
        #pragma unroll
        for (int ks = 0; ks < 2; ks++) {
            uint32_t a[2][4], bb[4][2];
            #pragma unroll
            for (int mt = 0; mt < 2; mt++) {
                const int r = wm * 32 + mt * 16 + g;
                a[mt][0] = *(const uint32_t*)(Ab + (r    ) * ASTR + ks * 16 + 2 * t);
                a[mt][1] = *(const uint32_t*)(Ab + (r + 8) * ASTR + ks * 16 + 2 * t);
                a[mt][2] = *(const uint32_t*)(Ab + (r    ) * ASTR + ks * 16 + 2 * t + 8);
                a[mt][3] = *(const uint32_t*)(Ab + (r + 8) * ASTR + ks * 16 + 2 * t + 8);
            }
            #pragma unroll
            for (int nt = 0; nt < 4; nt++) {
                const int r = wn * 32 + nt * 8 + g;
                bb[nt][0] = *(const uint32_t*)(Bb + r * BSTR + ks * 16 + 2 * t);
                bb[nt][1] = *(const uint32_t*)(Bb + r * BSTR + ks * 16 + 2 * t + 8);
            }
            #pragma unroll
            for (int mt = 0; mt < 2; mt++)
                #pragma unroll
                for (int nt = 0; nt < 4; nt++)
                    mma_f16(acc[mt][nt], a[mt], bb[nt][0], bb[nt][1]);
        }
        __syncthreads();
        if (kc + 2 < 8) {
            const int nk = (kc + 2) * 32;
            __half* Asb = As + (kc & 1) * 128 * ASTR;
            __half* Bsb = Bs + (kc & 1) * 64 * BSTR;
            cpa16(&Asb[ar0 * ASTR + ac0], Ag + (size_t)ar0 * 256 + nk + ac0);
            cpa16(&Asb[ar1 * ASTR + ac1], Ag + (size_t)ar1 * 256 + nk + ac1);
            cpa16(&Bsb[br * BSTR + bc],   Bg + (size_t)br * 256 + nk + bc);
        }
        CP_COMMIT();
    }

    #pragma unroll
    for (int mt = 0; mt < 2; mt++) {
        const int row0 = m0 + wm * 32 + mt * 16 + g;
        #pragma unroll
        for (int nt = 0; nt < 4; nt++) {
            const int n = n0 + wn * 32 + nt * 8 + 2 * t;
            const float2 bb = *reinterpret_cast<const float2*>(&bq[n]);
            __half2 h0 = __floats2half2_rn((acc[mt][nt][0] + bb.x) * QSCALE,
                                           (acc[mt][nt][1] + bb.y) * QSCALE);
            __half2 h1 = __floats2half2_rn((acc[mt][nt][2] + bb.x) * QSCALE,
                                           (acc[mt][nt][3] + bb.y) * QSCALE);
            *reinterpret_cast<__half2*>(&g_qh[(size_t) row0      * 256 + n]) = h0;
            *reinterpret_cast<__half2*>(&g_qh[(size_t)(row0 + 8) * 256 + n]) = h1;
        }
    }
}

__device__ __forceinline__ void kvproj_body(__half* sbuf, int bx, int by,
                                            const float* __restrict__ bk,
                                            const float* __restrict__ bv)
{
    __half* As  = sbuf;
    __half* Bks = sbuf + 2 * 128 * ASTR;
    __half* Bvs = Bks + 2 * 64 * BSTR;
    const int tid = threadIdx.x;
    const int w = tid >> 5, lane = tid & 31, g = lane >> 2, t = lane & 3;
    const int wm = w >> 1, wn = w & 1;
    const int m0 = by * 128, n0 = bx * 64;
    const int bidx = m0 >> 10, hw0 = m0 & 1023;

    const int ar0 = tid >> 2,         ac0 = (tid & 3) * 8;
    const int ar1 = (tid + 256) >> 2, ac1 = ac0;
    const int br  = tid >> 2,         bc  = (tid & 3) * 8;

    #pragma unroll
    for (int pc = 0; pc < 2; pc++) {
        const int k0 = pc * 32, v = k0 >> 8, c0 = k0 & 255;
        const __half* Ag = g_xt + ((size_t)(bidx * Vn + v) * 1024 + hw0) * 256 + c0;
        __half* Asb  = As  + pc * 128 * ASTR;
        __half* Bksb = Bks + pc * 64 * BSTR;
        __half* Bvsb = Bvs + pc * 64 * BSTR;
        cpa16(&Asb[ar0 * ASTR + ac0], Ag + (size_t)ar0 * 256 + ac0);
        cpa16(&Asb[ar1 * ASTR + ac1], Ag + (size_t)ar1 * 256 + ac1);
        cpa16(&Bksb[br * BSTR + bc], g_wkt + (size_t)(n0 + br) * 1536 + k0 + bc);
        cpa16(&Bvsb[br * BSTR + bc], g_wvt + (size_t)(n0 + br) * 1536 + k0 + bc);
        CP_COMMIT();
    }

    float acck[2][4][4] = {};
    float accv[2][4][4] = {};
    for (int kc = 0; kc < 48; kc++) {
        CP_WAIT1();
        __syncthreads();
        const __half* Ab  = As  + (kc & 1) * 128 * ASTR;
        const __half* Bkb = Bks + (kc & 1) * 64 * BSTR;
        const __half* Bvb = Bvs + (kc & 1) * 64 * BSTR;
        #pragma unroll
        for (int ks = 0; ks < 2; ks++) {
            uint32_t a[2][4], bkf[4][2], bvf[4][2];
            #pragma unroll
            for (int mt = 0; mt < 2; mt++) {
                const int r = wm * 32 + mt * 16 + g;
                a[mt][0] = *(const uint32_t*)(Ab + (r    ) * ASTR + ks * 16 + 2 * t);
                a[mt][1] = *(const uint32_t*)(Ab + (r + 8) * ASTR + ks * 16 + 2 * t);
                a[mt][2] = *(const uint32_t*)(Ab + (r    ) * ASTR + ks * 16 + 2 * t + 8);
                a[mt][3] = *(const uint32_t*)(Ab + (r + 8) * ASTR + ks * 16 + 2 * t + 8);
            }
            #pragma unroll
            for (int nt = 0; nt < 4; nt++) {
                const int r = wn * 32 + nt * 8 + g;
                bkf[nt][0] = *(const uint32_t*)(Bkb + r * BSTR + ks * 16 + 2 * t);
                bkf[nt][1] = *(const uint32_t*)(Bkb + r * BSTR + ks * 16 + 2 * t + 8);
                bvf[nt][0] = *(const uint32_t*)(Bvb + r * BSTR + ks * 16 + 2 * t);
                bvf[nt][1] = *(const uint32_t*)(Bvb + r * BSTR + ks * 16 + 2 * t + 8);
            }
            #pragma unroll
            for (int mt = 0; mt < 2; mt++)
                #pragma unroll
                for (int nt = 0; nt < 4; nt++) {
                    mma_f16(acck[mt][nt], a[mt], bkf[nt][0], bkf[nt][1]);
                    mma_f16(accv[mt][nt], a[mt], bvf[nt][0], bvf[nt][1]);
                }
        }
        __syncthreads();
        if (kc + 2 < 48) {
            const int k0 = (kc + 2) * 32, v = k0 >> 8, c0 = k0 & 255;
            const __half* Ag = g_xt + ((size_t)(bidx * Vn + v) * 1024 + hw0) * 256 + c0;
            __half* Asb  = As  + (kc & 1) * 128 * ASTR;
            __half* Bksb = Bks + (kc & 1) * 64 * BSTR;
            __half* Bvsb = Bvs + (kc & 1) * 64 * BSTR;
            cpa16(&Asb[ar0 * ASTR + ac0], Ag + (size_t)ar0 * 256 + ac0);
            cpa16(&Asb[ar1 * ASTR + ac1], Ag + (size_t)ar1 * 256 + ac1);
            cpa16(&Bksb[br * BSTR + bc], g_wkt + (size_t)(n0 + br) * 1536 + k0 + bc);
            cpa16(&Bvsb[br * BSTR + bc], g_wvt + (size_t)(n0 + br) * 1536 + k0 + bc);
        }
        CP_COMMIT();
    }

    #pragma unroll
    for (int mt = 0; mt < 2; mt++) {
        const int row0 = m0 + wm * 32 + mt * 16 + g;
        #pragma unroll
        for (int nt = 0; nt < 4; nt++) {
            const int n = n0 + wn * 32 + nt * 8 + 2 * t;
            const float2 bbk = *reinterpret_cast<const float2*>(&bk[n]);
            const float2 bbv = *reinterpret_cast<const float2*>(&bv[n]);
            #pragma unroll
            for (int rr = 0; rr < 2; rr++) {
                const int r  = row0 + rr * 8;
                const int hw = r & 1023, bb = r >> 10;
                __half2 kh = __floats2half2_rn(acck[mt][nt][2*rr]   + bbk.x,
                                               acck[mt][nt][2*rr+1] + bbk.y);
                *reinterpret_cast<__half2*>(
                    &g_kh[((size_t)(bb * 1024 + hw)) * 256 + n]) = kh;
                g_vt[(((size_t)(bb * 256 + n    )) << 10) + hw] =
                    __float2half(accv[mt][nt][2*rr]   + bbv.x);
                g_vt[(((size_t)(bb * 256 + n + 1)) << 10) + hw] =
                    __float2half(accv[mt][nt][2*rr+1] + bbv.y);
            }
        }
    }
}

__global__ void __launch_bounds__(256) qkvproj_kernel(const float* __restrict__ bq,
                                                      const float* __restrict__ bk,
                                                      const float* __restrict__ bv)
{
    __shared__ __align__(16) __half sbuf[2 * 128 * ASTR + 4 * 64 * BSTR];
    const int idx = blockIdx.x;
    if (idx < 128) {
        kvproj_body(sbuf, idx & 3, idx >> 2, bk, bv);
    } else {
        const int j = idx - 128;
        qproj_body(sbuf, j & 3, j >> 2, bq);
    }
}

// ---------------------------------------------------------------------------
// Flash attention, fp16-accumulator mma, warp = m32 (two m16 blocks sharing
// every K/V B-fragment load): CTA = 4 warps x 32 queries = 128 queries,
// 128 threads. Shared-pipe traffic per query halved vs m16 warps.
// ---------------------------------------------------------------------------
__global__ void __launch_bounds__(128, 4) attn_kernel()
{
    __shared__ __align__(16) __half Ks[2][64 * KVS];   // [key][dim]
    __shared__ __align__(16) __half Vt[2][64 * KVS];   // [dim][key]

    const int b  = blockIdx.z;
    const int h  = blockIdx.y;
    const int s0 = blockIdx.x * 128;
    const int tid = threadIdx.x;
    const int w = tid >> 5, lane = tid & 31, g = lane >> 2, t = lane & 3;

    const __half* kg = g_kh + (size_t)b * HWn * 256 + h * 64;          // stride 256
    const __half* vg = g_vt + (((size_t)(b * 256 + h * 64)) << 10);    // stride 1024

    // copy: 64 rows x 64 halves per tile; 128 thr -> each does 4 x 16B
    const int cr = tid >> 1;
    const int cc = (tid & 1) * 32;

    #pragma unroll
    for (int pc = 0; pc < 2; pc++) {
        const int jt = pc * 64;
        #pragma unroll
        for (int u = 0; u < 4; u++) {
            cpa16(&Ks[pc][cr * KVS + cc + u * 8], kg + (size_t)(jt + cr) * 256 + cc + u * 8);
            cpa16(&Vt[pc][cr * KVS + cc + u * 8], vg + (size_t)cr * 1024 + jt + cc + u * 8);
        }
        CP_COMMIT();
    }

    // Q fragments for two m16 blocks (rows w*32+blk*16+{g,g+8})
    uint32_t Qfr[2][4][4];
    #pragma unroll
    for (int blk = 0; blk < 2; blk++) {
        const __half* qbase = g_qh
            + ((size_t)(b * Sn + s0 + w * 32 + blk * 16)) * 256 + h * 64;
        #pragma unroll
        for (int ks = 0; ks < 4; ks++) {
            const int d0 = ks * 16 + 2 * t;
            Qfr[blk][ks][0] = *(const uint32_t*)(qbase + (size_t) g      * 256 + d0);
            Qfr[blk][ks][1] = *(const uint32_t*)(qbase + (size_t)(g + 8) * 256 + d0);
            Qfr[blk][ks][2] = *(const uint32_t*)(qbase + (size_t) g      * 256 + d0 + 8);
            Qfr[blk][ks][3] = *(const uint32_t*)(qbase + (size_t)(g + 8) * 256 + d0 + 8);
        }
    }

    uint32_t O0[2][8], O1[2][8];   // fp16x2 accumulators per block
    #pragma unroll
    for (int blk = 0; blk < 2; blk++)
        #pragma unroll
        for (int i = 0; i < 8; i++) { O0[blk][i] = 0u; O1[blk][i] = 0u; }
    float l[4] = {0.f, 0.f, 0.f, 0.f};   // rows: blk0{g,g+8}, blk1{g,g+8}
    const int rw = s0 + w * 32 + g;

    for (int it = 0; it < 16; it++) {
        const int jt = it * 64;
        CP_WAIT1();
        __syncthreads();
        const __half* Kb = Ks[it & 1];
        const __half* Vb = Vt[it & 1];
        const bool masked = (jt <= s0 + 130) && (jt + 66 >= s0);

        // ---- S = Q K^T (fp16 accum); both blocks share B-fragments ----
        uint32_t P0[2][8], P1[2][8];
        #pragma unroll
        for (int blk = 0; blk < 2; blk++)
            #pragma unroll
            for (int nt = 0; nt < 8; nt++) { P0[blk][nt] = 0u; P1[blk][nt] = 0u; }
        #pragma unroll
        for (int nt = 0; nt < 8; nt++) {
            const __half* kb = Kb + (nt * 8 + g) * KVS;
            #pragma unroll
            for (int ks = 0; ks < 4; ks++) {
                uint32_t b0 = *(const uint32_t*)(kb + ks * 16 + 2 * t);
                uint32_t b1 = *(const uint32_t*)(kb + ks * 16 + 2 * t + 8);
                mma_f16h(P0[0][nt], P1[0][nt], Qfr[0][ks], b0, b1);
                mma_f16h(P0[1][nt], P1[1][nt], Qfr[1][ks], b0, b1);
            }
        }

        // ---- mask: add -inf at windowed positions ----
        if (masked) {
            #pragma unroll
            for (int blk = 0; blk < 2; blk++) {
                const int ra = rw + blk * 16, rb = ra + 8;
                #pragma unroll
                for (int nt = 0; nt < 8; nt++) {
                    const int c = jt + nt * 8 + 2 * t;
                    uint32_t m0 = 0u, m1 = 0u;
                    if ((unsigned)(c     - ra + WIN) <= 2u * WIN) m0 |= HNINF;
                    if ((unsigned)(c + 1 - ra + WIN) <= 2u * WIN) m0 |= HNINF << 16;
                    if ((unsigned)(c     - rb + WIN) <= 2u * WIN) m1 |= HNINF;
                    if ((unsigned)(c + 1 - rb + WIN) <= 2u * WIN) m1 |= HNINF << 16;
                    if (m0) { __half2 s = __hadd2(u2h2(P0[blk][nt]), u2h2(m0));
                              P0[blk][nt] = *reinterpret_cast<uint32_t*>(&s); }
                    if (m1) { __half2 s = __hadd2(u2h2(P1[blk][nt]), u2h2(m1));
                              P1[blk][nt] = *reinterpret_cast<uint32_t*>(&s); }
                }
            }
        }

        // ---- P = exp2(S) in place; accumulate l ----
        #pragma unroll
        for (int blk = 0; blk < 2; blk++) {
            #pragma unroll
            for (int nt = 0; nt < 8; nt++) {
                P0[blk][nt] = h2exp2u(P0[blk][nt]);
                P1[blk][nt] = h2exp2u(P1[blk][nt]);
            }
            __half2 s0 = __hadd2(__hadd2(__hadd2(u2h2(P0[blk][0]), u2h2(P0[blk][1])),
                                         __hadd2(u2h2(P0[blk][2]), u2h2(P0[blk][3]))),
                                 __hadd2(__hadd2(u2h2(P0[blk][4]), u2h2(P0[blk][5])),
                                         __hadd2(u2h2(P0[blk][6]), u2h2(P0[blk][7]))));
            __half2 s1 = __hadd2(__hadd2(__hadd2(u2h2(P1[blk][0]), u2h2(P1[blk][1])),
                                         __hadd2(u2h2(P1[blk][2]), u2h2(P1[blk][3]))),
                                 __hadd2(__hadd2(u2h2(P1[blk][4]), u2h2(P1[blk][5])),
                                         __hadd2(u2h2(P1[blk][6]), u2h2(P1[blk][7]))));
            float2 f0 = __half22float2(s0); l[blk * 2    ] += f0.x + f0.y;
            float2 f1 = __half22float2(s1); l[blk * 2 + 1] += f1.x + f1.y;
        }

        // ---- O += P V; both blocks share V B-fragments ----
        #pragma unroll
        for (int m = 0; m < 4; m++) {
            uint32_t a0[4] = { P0[0][2*m], P1[0][2*m], P0[0][2*m+1], P1[0][2*m+1] };
            uint32_t a1[4] = { P0[1][2*m], P1[1][2*m], P0[1][2*m+1], P1[1][2*m+1] };
            #pragma unroll
            for (int dn = 0; dn < 8; dn++) {
                const __half* vb = Vb + (dn * 8 + g) * KVS + m * 16 + 2 * t;
                uint32_t b0 = *(const uint32_t*)(vb);
                uint32_t b1 = *(const uint32_t*)(vb + 8);
                mma_f16h(O0[0][dn], O1[0][dn], a0, b0, b1);
                mma_f16h(O0[1][dn], O1[1][dn], a1, b0, b1);
            }
        }

        __syncthreads();
        if (it + 2 < 16) {
            const int nj = jt + 128, buf = it & 1;
            #pragma unroll
            for (int u = 0; u < 4; u++) {
                cpa16(&Ks[buf][cr * KVS + cc + u * 8], kg + (size_t)(nj + cr) * 256 + cc + u * 8);
                cpa16(&Vt[buf][cr * KVS + cc + u * 8], vg + (size_t)cr * 1024 + nj + cc + u * 8);
            }
        }
        CP_COMMIT();
    }

    // ---- epilogue: reduce l across t-group, normalize, store fp16 ----
    #pragma unroll
    for (int i = 0; i < 4; i++) {
        l[i] += __shfl_xor_sync(0xffffffffu, l[i], 1);
        l[i] += __shfl_xor_sync(0xffffffffu, l[i], 2);
    }
    #pragma unroll
    for (int blk = 0; blk < 2; blk++) {
        const float inv0 = 1.f / l[blk * 2], inv1 = 1.f / l[blk * 2 + 1];
        __half* ob = g_aoh
            + ((size_t)(b * Sn + s0 + w * 32 + blk * 16)) * 256 + h * 64;
        #pragma unroll
        for (int nt = 0; nt < 8; nt++) {
            const int n = nt * 8 + 2 * t;
            float2 f0 = __half22float2(u2h2(O0[blk][nt]));
            float2 f1 = __half22float2(u2h2(O1[blk][nt]));
            *reinterpret_cast<__half2*>(&ob[(size_t) g      * 256 + n]) =
                __floats2half2_rn(f0.x * inv0, f0.y * inv0);
            *reinterpret_cast<__half2*>(&ob[(size_t)(g + 8) * 256 + n]) =
                __floats2half2_rn(f1.x * inv1, f1.y * inv1);
        }
    }
}

// ---------------------------------------------------------------------------
// Output projection + reshape-scatter + residual (fp16 GEMM, fp32 epilogue)
// ---------------------------------------------------------------------------
__global__ void __launch_bounds__(256) oproj_kernel(const float* __restrict__ x,
                                                    const float* __restrict__ bo,
                                                    float* __restrict__ out)
{
    __shared__ __align__(16) __half As[2][128 * ASTR];
    __shared__ __align__(16) __half Bs[2][64 * BSTR];
    const int tid = threadIdx.x;
    const int w = tid >> 5, lane = tid & 31, g = lane >> 2, t = lane & 3;
    const int wm = w >> 1, wn = w & 1;
    const int m0 = blockIdx.y * 128, n0 = blockIdx.x * 64;
    const __half* Ag = g_aoh + (size_t)m0 * 256;
    const __half* Bg = g_wot + (size_t)n0 * 256;

    const int ar0 = tid >> 2,         ac0 = (tid & 3) * 8;
    const int ar1 = (tid + 256) >> 2, ac1 = ac0;
    const int br  = tid >> 2,         bc  = (tid & 3) * 8;

    #pragma unroll
    for (int pc = 0; pc < 2; pc++) {
        cpa16(&As[pc][ar0 * ASTR + ac0], Ag + (size_t)ar0 * 256 + pc * 32 + ac0);
        cpa16(&As[pc][ar1 * ASTR + ac1], Ag + (size_t)ar1 * 256 + pc * 32 + ac1);
        cpa16(&Bs[pc][br * BSTR + bc],   Bg + (size_t)br * 256 + pc * 32 + bc);
        CP_COMMIT();
    }

    float acc[2][4][4] = {};
    for (int kc = 0; kc < 8; kc++) {
        CP_WAIT1();
        __syncthreads();
        const __half* Ab = As[kc & 1];
        const __half* Bb = Bs[kc & 1];
        #pragma unroll
        for (int ks = 0; ks < 2; ks++) {
            uint32_t a[2][4], bb[4][2];
            #pragma unroll
            for (int mt = 0; mt < 2; mt++) {
                const int r = wm * 32 + mt * 16 + g;
                a[mt][0] = *(const uint32_t*)(Ab + (r    ) * ASTR + ks * 16 + 2 * t);
                a[mt][1] = *(const uint32_t*)(Ab + (r + 8) * ASTR + ks * 16 + 2 * t);
                a[mt][2] = *(const uint32_t*)(Ab + (r    ) * ASTR + ks * 16 + 2 * t + 8);
                a[mt][3] = *(const uint32_t*)(Ab + (r + 8) * ASTR + ks * 16 + 2 * t + 8);
            }
            #pragma unroll
            for (int nt = 0; nt < 4; nt++) {
                const int r = wn * 32 + nt * 8 + g;
                bb[nt][0] = *(const uint32_t*)(Bb + r * BSTR + ks * 16 + 2 * t);
                bb[nt][1] = *(const uint32_t*)(Bb + r * BSTR + ks * 16 + 2 * t + 8);
            }
            #pragma unroll
            for (int mt = 0; mt < 2; mt++)
                #pragma unroll
                for (int nt = 0; nt < 4; nt++)
                    mma_f16(acc[mt][nt], a[mt], bb[nt][0], bb[nt][1]);
        }
        __syncthreads();
        if (kc + 2 < 8) {
            const int nk = kc + 2, buf = kc & 1;
            cpa16(&As[buf][ar0 * ASTR + ac0], Ag + (size_t)ar0 * 256 + nk * 32 + ac0);
            cpa16(&As[buf][ar1 * ASTR + ac1], Ag + (size_t)ar1 * 256 + nk * 32 + ac1);
            cpa16(&Bs[buf][br * BSTR + bc],   Bg + (size_t)br * 256 + nk * 32 + bc);
        }
        CP_COMMIT();
    }

    #pragma unroll
    for (int mt = 0; mt < 2; mt++) {
        const int row0 = m0 + wm * 32 + mt * 16 + g;
        #pragma unroll
        for (int nt = 0; nt < 4; nt++) {
            const int n = n0 + wn * 32 + nt * 8 + 2 * t;
            const float2 bb = *reinterpret_cast<const float2*>(&bo[n]);
            #pragma unroll
            for (int rr = 0; rr < 2; rr++) {
                const int m  = row0 + rr * 8;
                const int bv = m >> 10;
                const int hw = m & 1023;
                const size_t flat = ((size_t)(bv * 256 + (hw >> 2))) * 1024
                                  + (size_t)(hw & 3) * 256 + n;
                const float2 xr = *reinterpret_cast<const float2*>(&x[flat]);
                float2 o;
                o.x = acc[mt][nt][2*rr]   + bb.x + xr.x;
                o.y = acc[mt][nt][2*rr+1] + bb.y + xr.y;
                *reinterpret_cast<float2*>(&out[flat]) = o;
            }
        }
    }
}

// ---------------------------------------------------------------------------
extern "C" void kernel_launch(void* const* d_in, const int* in_sizes, int n_in,
                              void* d_out, int out_size)
{
    const float* x  = (const float*)d_in[0];
    const float* Wq = (const float*)d_in[1];
    const float* bq = (const float*)d_in[2];
    const float* Wk = (const float*)d_in[3];
    const float* bk = (const float*)d_in[4];
    const float* Wv = (const float*)d_in[5];
    const float* bv = (const float*)d_in[6];
    const float* Wo = (const float*)d_in[7];
    const float* bo = (const float*)d_in[8];
    float* out = (float*)d_out;

    prep_x <<<dim3(32, 8, 24), dim3(32, 8)>>>(x);
    prep_w <<<dim3(8, 48, 4),  dim3(32, 8)>>>(Wq, Wk, Wv, Wo);
    qkvproj_kernel<<<896, 256>>>(bq, bk, bv);
    attn_kernel  <<<dim3(48, 4, 4), 128>>>();
    oproj_kernel <<<dim3(4, 192), 256>>>(x, bo, out);
}

// round 14
// speedup vs baseline: 1.0372x; 1.0372x over previous
#include <cuda_runtime.h>
#include <cuda_fp16.h>
#include <cstdint>

// Problem constants
#define Bn   4
#define Vn   6
#define Cn   256
#define HWn  1024
#define Sn   6144
#define WIN  3
#define QSCALE (0.125f * 1.44269504f)   // 1/sqrt(64) * log2(e)

// Scratch (__device__ globals; allocation-free rule)
__device__ __half g_xt [(size_t)Bn * Vn * HWn * Cn];  // [bv][hw][c]
__device__ __half g_qh [(size_t)Bn * Sn  * Cn];       // [B,S,C]  (scaled by QSCALE)
__device__ __half g_kh [(size_t)Bn * HWn * Cn];       // [B,HW,C]
__device__ __half g_vt [(size_t)Bn * Cn  * HWn];      // [B,C,HW] (transposed)
__device__ __half g_aoh[(size_t)Bn * Sn  * Cn];       // [B,S,C]
__device__ __half g_wqt[256 * 256];                   // W^T [n][k]
__device__ __half g_wkt[256 * 1536];
__device__ __half g_wvt[256 * 1536];
__device__ __half g_wot[256 * 256];

// ---------------------------------------------------------------------------
// helpers
// ---------------------------------------------------------------------------
__device__ __forceinline__ void mma_f16(float* d, const uint32_t* a,
                                        uint32_t b0, uint32_t b1)
{
    asm volatile(
        "mma.sync.aligned.m16n8k16.row.col.f32.f16.f16.f32 "
        "{%0,%1,%2,%3}, {%4,%5,%6,%7}, {%8,%9}, {%0,%1,%2,%3};"
        : "+f"(d[0]), "+f"(d[1]), "+f"(d[2]), "+f"(d[3])
        : "r"(a[0]), "r"(a[1]), "r"(a[2]), "r"(a[3]), "r"(b0), "r"(b1));
}

// fp16-accumulator mma: D,C are 2 regs (4 halves). 2x tensor throughput.
__device__ __forceinline__ void mma_f16h(uint32_t& d0, uint32_t& d1,
                                         const uint32_t* a,
                                         uint32_t b0, uint32_t b1)
{
    asm volatile(
        "mma.sync.aligned.m16n8k16.row.col.f16.f16.f16.f16 "
        "{%0,%1}, {%2,%3,%4,%5}, {%6,%7}, {%0,%1};"
        : "+r"(d0), "+r"(d1)
        : "r"(a[0]), "r"(a[1]), "r"(a[2]), "r"(a[3]), "r"(b0), "r"(b1));
}

__device__ __forceinline__ uint32_t h2exp2u(uint32_t x)
{
    __half2 h = h2exp2(*reinterpret_cast<__half2*>(&x));
    return *reinterpret_cast<uint32_t*>(&h);
}

__device__ __forceinline__ __half2 u2h2(uint32_t x)
{
    return *reinterpret_cast<__half2*>(&x);
}

__device__ __forceinline__ void cpa16(__half* dst, const __half* src)
{
    uint32_t s = (uint32_t)__cvta_generic_to_shared(dst);
    asm volatile("cp.async.cg.shared.global [%0], [%1], 16;" :: "r"(s), "l"(src));
}
#define CP_COMMIT() asm volatile("cp.async.commit_group;")
#define CP_WAIT1()  asm volatile("cp.async.wait_group 1;")

#define ASTR 40     // halves per A smem row (32 k + 8 pad)
#define BSTR 40
#define KVS  72     // halves per KV smem row (64 + 8 pad)
#define HNINF 0xFC00u   // fp16 -inf bits

// ---------------------------------------------------------------------------
// prep (merged): blocks [0,6144) transpose x -> fp16 [bv][hw][c];
// blocks [6144,7680) transpose weights W [K][256] -> W^T fp16 [256][K].
// ---------------------------------------------------------------------------
__global__ void prep_all(const float* __restrict__ x,
                         const float* __restrict__ Wq, const float* __restrict__ Wk,
                         const float* __restrict__ Wv, const float* __restrict__ Wo)
{
    __shared__ float ts[32][33];
    const int tx = threadIdx.x, ty = threadIdx.y;
    const int idx = blockIdx.x;
    if (idx < 6144) {
        const int hw0 = (idx & 31) * 32;
        const int c0  = ((idx >> 5) & 7) * 32;
        const int bv  = idx >> 8;
        #pragma unroll
        for (int r = 0; r < 4; r++) {
            const int c = c0 + ty * 4 + r;
            ts[ty * 4 + r][tx] = x[((size_t)bv * 256 + c) * 1024 + hw0 + tx];
        }
        __syncthreads();
        #pragma unroll
        for (int r = 0; r < 4; r++) {
            const int hw = hw0 + ty * 4 + r;
            g_xt[((size_t)bv * 1024 + hw) * 256 + c0 + tx] =
                __float2half(ts[tx][ty * 4 + r]);
        }
    } else {
        const int j  = idx - 6144;
        const int n0 = (j & 7) * 32;
        const int k0 = ((j >> 3) % 48) * 32;
        const int ws = j / 384;
        const float* src; __half* dst; int K;
        switch (ws) {
            case 0:  src = Wq; dst = g_wqt; K = 256;  break;
            case 1:  src = Wk; dst = g_wkt; K = 1536; break;
            case 2:  src = Wv; dst = g_wvt; K = 1536; break;
            default: src = Wo; dst = g_wot; K = 256;  break;
        }
        if (k0 >= K) return;
        #pragma unroll
        for (int r = 0; r < 4; r++)
            ts[ty * 4 + r][tx] = src[(size_t)(k0 + ty * 4 + r) * 256 + n0 + tx];
        __syncthreads();
        #pragma unroll
        for (int r = 0; r < 4; r++)
            dst[(size_t)(n0 + ty * 4 + r) * K + k0 + tx] =
                __float2half(ts[tx][ty * 4 + r]);
    }
}

// ---------------------------------------------------------------------------
// Fused Q + KV projection launch (unchanged, best config).
// ---------------------------------------------------------------------------
__device__ __forceinline__ void qproj_body(__half* sbuf, int bx, int by,
                                           const float* __restrict__ bq)
{
    __half* As = sbuf;
    __half* Bs = sbuf + 2 * 128 * ASTR;
    const int tid = threadIdx.x;
    const int w = tid >> 5, lane = tid & 31, g = lane >> 2, t = lane & 3;
    const int wm = w >> 1, wn = w & 1;
    const int m0 = by * 128, n0 = bx * 64;
    const __half* Ag = g_xt + (size_t)m0 * 256;
    const __half* Bg = g_wqt + (size_t)n0 * 256;

    const int ar0 = tid >> 2,           ac0 = (tid & 3) * 8;
    const int ar1 = (tid + 256) >> 2,   ac1 = ac0;
    const int br  = tid >> 2,           bc  = (tid & 3) * 8;

    #pragma unroll
    for (int pc = 0; pc < 2; pc++) {
        __half* Asb = As + pc * 128 * ASTR;
        __half* Bsb = Bs + pc * 64 * BSTR;
        cpa16(&Asb[ar0 * ASTR + ac0], Ag + (size_t)ar0 * 256 + pc * 32 + ac0);
        cpa16(&Asb[ar1 * ASTR + ac1], Ag + (size_t)ar1 * 256 + pc * 32 + ac1);
        cpa16(&Bsb[br * BSTR + bc],   Bg + (size_t)br * 256 + pc * 32 + bc);
        CP_COMMIT();
    }

    float acc[2][4][4] = {};
    for (int kc = 0; kc < 8; kc++) {
        CP_WAIT1();
        __syncthreads();
        const __half* Ab = As + (kc & 1) * 128 * ASTR;
        const __half* Bb = Bs + (kc & 1) * 64 * BSTR;
        #pragma unroll
        for (int ks = 0; ks < 2; ks++) {
            uint32_t a[2][4], bb[4][2];
            #pragma unroll
            for (int mt = 0; mt < 2; mt++) {
                const int r = wm * 32 + mt * 16 + g;
                a[mt][0] = *(const uint32_t*)(Ab + (r    ) * ASTR + ks * 16 + 2 * t);
                a[mt][1] = *(const uint32_t*)(Ab + (r + 8) * ASTR + ks * 16 + 2 * t);
                a[mt][2] = *(const uint32_t*)(Ab + (r    ) * ASTR + ks * 16 + 2 * t + 8);
                a[mt][3] = *(const uint32_t*)(Ab + (r + 8) * ASTR + ks * 16 + 2 * t + 8);
            }
            #pragma unroll
            for (int nt = 0; nt < 4; nt++) {
                const int r = wn * 32 + nt * 8 + g;
                bb[nt][0] = *(const uint32_t*)(Bb + r * BSTR + ks * 16 + 2 * t);
                bb[nt][1] = *(const uint32_t*)(Bb + r * BSTR + ks * 16 + 2 * t + 8);
            }
            #pragma unroll
            for (int mt = 0; mt < 2; mt++)
                #pragma unroll
                for (int nt = 0; nt < 4; nt++)
                    mma_f16(acc[mt][nt], a[mt], bb[nt][0], bb[nt][1]);
        }
        __syncthreads();
        if (kc + 2 < 8) {
            const int nk = (kc + 2) * 32;
            __half* Asb = As + (kc & 1) * 128 * ASTR;
            __half* Bsb = Bs + (kc & 1) * 64 * BSTR;
            cpa16(&Asb[ar0 * ASTR + ac0], Ag + (size_t)ar0 * 256 + nk + ac0);
            cpa16(&Asb[ar1 * ASTR + ac1], Ag + (size_t)ar1 * 256 + nk + ac1);
            cpa16(&Bsb[br * BSTR + bc],   Bg + (size_t)br * 256 + nk + bc);
        }
        CP_COMMIT();
    }

    #pragma unroll
    for (int mt = 0; mt < 2; mt++) {
        const int row0 = m0 + wm * 32 + mt * 16 + g;
        #pragma unroll
        for (int nt = 0; nt < 4; nt++) {
            const int n = n0 + wn * 32 + nt * 8 + 2 * t;
            const float2 bb = *reinterpret_cast<const float2*>(&bq[n]);
            __half2 h0 = __floats2half2_rn((acc[mt][nt][0] + bb.x) * QSCALE,
                                           (acc[mt][nt][1] + bb.y) * QSCALE);
            __half2 h1 = __floats2half2_rn((acc[mt][nt][2] + bb.x) * QSCALE,
                                           (acc[mt][nt][3] + bb.y) * QSCALE);
            *reinterpret_cast<__half2*>(&g_qh[(size_t) row0      * 256 + n]) = h0;
            *reinterpret_cast<__half2*>(&g_qh[(size_t)(row0 + 8) * 256 + n]) = h1;
        }
    }
}

__device__ __forceinline__ void kvproj_body(__half* sbuf, int bx, int by,
                                            const float* __restrict__ bk,
                                            const float* __restrict__ bv)
{
    __half* As  = sbuf;
    __half* Bks = sbuf + 2 * 128 * ASTR;
    __half* Bvs = Bks + 2 * 64 * BSTR;
    const int tid = threadIdx.x;
    const int w = tid >> 5, lane = tid & 31, g = lane >> 2, t = lane & 3;
    const int wm = w >> 1, wn = w & 1;
    const int m0 = by * 128, n0 = bx * 64;
    const int bidx = m0 >> 10, hw0 = m0 & 1023;

    const int ar0 = tid >> 2,         ac0 = (tid & 3) * 8;
    const int ar1 = (tid + 256) >> 2, ac1 = ac0;
    const int br  = tid >> 2,         bc  = (tid & 3) * 8;

    #pragma unroll
    for (int pc = 0; pc < 2; pc++) {
        const int k0 = pc * 32, v = k0 >> 8, c0 = k0 & 255;
        const __half* Ag = g_xt + ((size_t)(bidx * Vn + v) * 1024 + hw0) * 256 + c0;
        __half* Asb  = As  + pc * 128 * ASTR;
        __half* Bksb = Bks + pc * 64 * BSTR;
        __half* Bvsb = Bvs + pc * 64 * BSTR;
        cpa16(&Asb[ar0 * ASTR + ac0], Ag + (size_t)ar0 * 256 + ac0);
        cpa16(&Asb[ar1 * ASTR + ac1], Ag + (size_t)ar1 * 256 + ac1);
        cpa16(&Bksb[br * BSTR + bc], g_wkt + (size_t)(n0 + br) * 1536 + k0 + bc);
        cpa16(&Bvsb[br * BSTR + bc], g_wvt + (size_t)(n0 + br) * 1536 + k0 + bc);
        CP_COMMIT();
    }

    float acck[2][4][4] = {};
    float accv[2][4][4] = {};
    for (int kc = 0; kc < 48; kc++) {
        CP_WAIT1();
        __syncthreads();
        const __half* Ab  = As  + (kc & 1) * 128 * ASTR;
        const __half* Bkb = Bks + (kc & 1) * 64 * BSTR;
        const __half* Bvb = Bvs + (kc & 1) * 64 * BSTR;
        #pragma unroll
        for (int ks = 0; ks < 2; ks++) {
            uint32_t a[2][4], bkf[4][2], bvf[4][2];
            #pragma unroll
            for (int mt = 0; mt < 2; mt++) {
                const int r = wm * 32 + mt * 16 + g;
                a[mt][0] = *(const uint32_t*)(Ab + (r    ) * ASTR + ks * 16 + 2 * t);
                a[mt][1] = *(const uint32_t*)(Ab + (r + 8) * ASTR + ks * 16 + 2 * t);
                a[mt][2] = *(const uint32_t*)(Ab + (r    ) * ASTR + ks * 16 + 2 * t + 8);
                a[mt][3] = *(const uint32_t*)(Ab + (r + 8) * ASTR + ks * 16 + 2 * t + 8);
            }
            #pragma unroll
            for (int nt = 0; nt < 4; nt++) {
                const int r = wn * 32 + nt * 8 + g;
                bkf[nt][0] = *(const uint32_t*)(Bkb + r * BSTR + ks * 16 + 2 * t);
                bkf[nt][1] = *(const uint32_t*)(Bkb + r * BSTR + ks * 16 + 2 * t + 8);
                bvf[nt][0] = *(const uint32_t*)(Bvb + r * BSTR + ks * 16 + 2 * t);
                bvf[nt][1] = *(const uint32_t*)(Bvb + r * BSTR + ks * 16 + 2 * t + 8);
            }
            #pragma unroll
            for (int mt = 0; mt < 2; mt++)
                #pragma unroll
                for (int nt = 0; nt < 4; nt++) {
                    mma_f16(acck[mt][nt], a[mt], bkf[nt][0], bkf[nt][1]);
                    mma_f16(accv[mt][nt], a[mt], bvf[nt][0], bvf[nt][1]);
                }
        }
        __syncthreads();
        if (kc + 2 < 48) {
            const int k0 = (kc + 2) * 32, v = k0 >> 8, c0 = k0 & 255;
            const __half* Ag = g_xt + ((size_t)(bidx * Vn + v) * 1024 + hw0) * 256 + c0;
            __half* Asb  = As  + (kc & 1) * 128 * ASTR;
            __half* Bksb = Bks + (kc & 1) * 64 * BSTR;
            __half* Bvsb = Bvs + (kc & 1) * 64 * BSTR;
            cpa16(&Asb[ar0 * ASTR + ac0], Ag + (size_t)ar0 * 256 + ac0);
            cpa16(&Asb[ar1 * ASTR + ac1], Ag + (size_t)ar1 * 256 + ac1);
            cpa16(&Bksb[br * BSTR + bc], g_wkt + (size_t)(n0 + br) * 1536 + k0 + bc);
            cpa16(&Bvsb[br * BSTR + bc], g_wvt + (size_t)(n0 + br) * 1536 + k0 + bc);
        }
        CP_COMMIT();
    }

    #pragma unroll
    for (int mt = 0; mt < 2; mt++) {
        const int row0 = m0 + wm * 32 + mt * 16 + g;
        #pragma unroll
        for (int nt = 0; nt < 4; nt++) {
            const int n = n0 + wn * 32 + nt * 8 + 2 * t;
            const float2 bbk = *reinterpret_cast<const float2*>(&bk[n]);
            const float2 bbv = *reinterpret_cast<const float2*>(&bv[n]);
            #pragma unroll
            for (int rr = 0; rr < 2; rr++) {
                const int r  = row0 + rr * 8;
                const int hw = r & 1023, bb = r >> 10;
                __half2 kh = __floats2half2_rn(acck[mt][nt][2*rr]   + bbk.x,
                                               acck[mt][nt][2*rr+1] + bbk.y);
                *reinterpret_cast<__half2*>(
                    &g_kh[((size_t)(bb * 1024 + hw)) * 256 + n]) = kh;
                g_vt[(((size_t)(bb * 256 + n    )) << 10) + hw] =
                    __float2half(accv[mt][nt][2*rr]   + bbv.x);
                g_vt[(((size_t)(bb * 256 + n + 1)) << 10) + hw] =
                    __float2half(accv[mt][nt][2*rr+1] + bbv.y);
            }
        }
    }
}

__global__ void __launch_bounds__(256) qkvproj_kernel(const float* __restrict__ bq,
                                                      const float* __restrict__ bk,
                                                      const float* __restrict__ bv)
{
    __shared__ __align__(16) __half sbuf[2 * 128 * ASTR + 4 * 64 * BSTR];
    const int idx = blockIdx.x;
    if (idx < 128) {
        kvproj_body(sbuf, idx & 3, idx >> 2, bk, bv);
    } else {
        const int j = idx - 128;
        qproj_body(sbuf, j & 3, j >> 2, bq);
    }
}

// ---------------------------------------------------------------------------
// Flash attention, fp16-accumulator mma, SOFTWARE-PIPELINED tile body:
// QK_A(nt0-3) -> exp2_A -> QK_B(nt4-7) -> PV_A(m0,1) -> exp2_B -> PV_B(m2,3).
// The independent MMA block behind each exp2 phase keeps the tensor pipe fed.
// CTA = 128 queries (8 warps x m16); 16 key-tiles of 64; 2-stage cp.async.
// ---------------------------------------------------------------------------
__global__ void __launch_bounds__(256) attn_kernel()
{
    __shared__ __align__(16) __half Ks[2][64 * KVS];   // [key][dim]
    __shared__ __align__(16) __half Vt[2][64 * KVS];   // [dim][key]

    const int b  = blockIdx.z;
    const int h  = blockIdx.y;
    const int s0 = blockIdx.x * 128;
    const int tid = threadIdx.x;
    const int w = tid >> 5, lane = tid & 31, g = lane >> 2, t = lane & 3;

    const __half* kg = g_kh + (size_t)b * HWn * 256 + h * 64;          // stride 256
    const __half* vg = g_vt + (((size_t)(b * 256 + h * 64)) << 10);    // stride 1024

    const int cr0 = tid >> 3,         cc0 = (tid & 7) * 8;
    const int cr1 = (tid + 256) >> 3, cc1 = cc0;

    #pragma unroll
    for (int pc = 0; pc < 2; pc++) {
        const int jt = pc * 64;
        cpa16(&Ks[pc][cr0 * KVS + cc0], kg + (size_t)(jt + cr0) * 256 + cc0);
        cpa16(&Ks[pc][cr1 * KVS + cc1], kg + (size_t)(jt + cr1) * 256 + cc1);
        cpa16(&Vt[pc][cr0 * KVS + cc0], vg + (size_t)cr0 * 1024 + jt + cc0);
        cpa16(&Vt[pc][cr1 * KVS + cc1], vg + (size_t)cr1 * 1024 + jt + cc1);
        CP_COMMIT();
    }

    // Q fragments (already scaled by QSCALE in qproj)
    const __half* qbase = g_qh + ((size_t)(b * Sn + s0 + w * 16)) * 256 + h * 64;
    uint32_t Qfr[4][4];
    #pragma unroll
    for (int ks = 0; ks < 4; ks++) {
        const int d0 = ks * 16 + 2 * t;
        Qfr[ks][0] = *(const uint32_t*)(qbase + (size_t) g      * 256 + d0);
        Qfr[ks][1] = *(const uint32_t*)(qbase + (size_t)(g + 8) * 256 + d0);
        Qfr[ks][2] = *(const uint32_t*)(qbase + (size_t) g      * 256 + d0 + 8);
        Qfr[ks][3] = *(const uint32_t*)(qbase + (size_t)(g + 8) * 256 + d0 + 8);
    }

    uint32_t O0[8], O1[8];   // fp16x2 accumulators: O0=row r0, O1=row r1
    #pragma unroll
    for (int i = 0; i < 8; i++) { O0[i] = 0u; O1[i] = 0u; }
    float l0 = 0.f, l1 = 0.f;
    const int r0 = s0 + w * 16 + g, r1 = r0 + 8;

    for (int it = 0; it < 16; it++) {
        const int jt = it * 64;
        CP_WAIT1();
        __syncthreads();
        const __half* Kb = Ks[it & 1];
        const __half* Vb = Vt[it & 1];
        const bool masked = (jt <= s0 + 130) && (jt + 66 >= s0);

        uint32_t P0[8], P1[8];

        // ---- QK half A (keys 0..31, nt 0..3) ----
        #pragma unroll
        for (int nt = 0; nt < 4; nt++) {
            P0[nt] = 0u; P1[nt] = 0u;
            const __half* kb = Kb + (nt * 8 + g) * KVS;
            #pragma unroll
            for (int ks = 0; ks < 4; ks++) {
                uint32_t b0 = *(const uint32_t*)(kb + ks * 16 + 2 * t);
                uint32_t b1 = *(const uint32_t*)(kb + ks * 16 + 2 * t + 8);
                mma_f16h(P0[nt], P1[nt], Qfr[ks], b0, b1);
            }
        }

        // ---- mask + exp2 + l for half A ----
        if (masked) {
            #pragma unroll
            for (int nt = 0; nt < 4; nt++) {
                const int c = jt + nt * 8 + 2 * t;
                uint32_t m0 = 0u, m1 = 0u;
                if ((unsigned)(c     - r0 + WIN) <= 2u * WIN) m0 |= HNINF;
                if ((unsigned)(c + 1 - r0 + WIN) <= 2u * WIN) m0 |= HNINF << 16;
                if ((unsigned)(c     - r1 + WIN) <= 2u * WIN) m1 |= HNINF;
                if ((unsigned)(c + 1 - r1 + WIN) <= 2u * WIN) m1 |= HNINF << 16;
                if (m0) { __half2 s = __hadd2(u2h2(P0[nt]), u2h2(m0));
                          P0[nt] = *reinterpret_cast<uint32_t*>(&s); }
                if (m1) { __half2 s = __hadd2(u2h2(P1[nt]), u2h2(m1));
                          P1[nt] = *reinterpret_cast<uint32_t*>(&s); }
            }
        }
        #pragma unroll
        for (int nt = 0; nt < 4; nt++) {
            P0[nt] = h2exp2u(P0[nt]);
            P1[nt] = h2exp2u(P1[nt]);
        }
        {
            __half2 s0 = __hadd2(__hadd2(u2h2(P0[0]), u2h2(P0[1])),
                                 __hadd2(u2h2(P0[2]), u2h2(P0[3])));
            __half2 s1 = __hadd2(__hadd2(u2h2(P1[0]), u2h2(P1[1])),
                                 __hadd2(u2h2(P1[2]), u2h2(P1[3])));
            float2 f0 = __half22float2(s0); l0 += f0.x + f0.y;
            float2 f1 = __half22float2(s1); l1 += f1.x + f1.y;
        }

        // ---- QK half B (keys 32..63, nt 4..7) — overlaps exp2_A latency ----
        #pragma unroll
        for (int nt = 4; nt < 8; nt++) {
            P0[nt] = 0u; P1[nt] = 0u;
            const __half* kb = Kb + (nt * 8 + g) * KVS;
            #pragma unroll
            for (int ks = 0; ks < 4; ks++) {
                uint32_t b0 = *(const uint32_t*)(kb + ks * 16 + 2 * t);
                uint32_t b1 = *(const uint32_t*)(kb + ks * 16 + 2 * t + 8);
                mma_f16h(P0[nt], P1[nt], Qfr[ks], b0, b1);
            }
        }

        // ---- PV half A (m = 0,1) ----
        #pragma unroll
        for (int m = 0; m < 2; m++) {
            uint32_t a[4] = { P0[2*m], P1[2*m], P0[2*m+1], P1[2*m+1] };
            #pragma unroll
            for (int dn = 0; dn < 8; dn++) {
                const __half* vb = Vb + (dn * 8 + g) * KVS + m * 16 + 2 * t;
                uint32_t b0 = *(const uint32_t*)(vb);
                uint32_t b1 = *(const uint32_t*)(vb + 8);
                mma_f16h(O0[dn], O1[dn], a, b0, b1);
            }
        }

        // ---- mask + exp2 + l for half B — overlaps PV_A issue ----
        if (masked) {
            #pragma unroll
            for (int nt = 4; nt < 8; nt++) {
                const int c = jt + nt * 8 + 2 * t;
                uint32_t m0 = 0u, m1 = 0u;
                if ((unsigned)(c     - r0 + WIN) <= 2u * WIN) m0 |= HNINF;
                if ((unsigned)(c + 1 - r0 + WIN) <= 2u * WIN) m0 |= HNINF << 16;
                if ((unsigned)(c     - r1 + WIN) <= 2u * WIN) m1 |= HNINF;
                if ((unsigned)(c + 1 - r1 + WIN) <= 2u * WIN) m1 |= HNINF << 16;
                if (m0) { __half2 s = __hadd2(u2h2(P0[nt]), u2h2(m0));
                          P0[nt] = *reinterpret_cast<uint32_t*>(&s); }
                if (m1) { __half2 s = __hadd2(u2h2(P1[nt]), u2h2(m1));
                          P1[nt] = *reinterpret_cast<uint32_t*>(&s); }
            }
        }
        #pragma unroll
        for (int nt = 4; nt < 8; nt++) {
            P0[nt] = h2exp2u(P0[nt]);
            P1[nt] = h2exp2u(P1[nt]);
        }
        {
            __half2 s0 = __hadd2(__hadd2(u2h2(P0[4]), u2h2(P0[5])),
                                 __hadd2(u2h2(P0[6]), u2h2(P0[7])));
            __half2 s1 = __hadd2(__hadd2(u2h2(P1[4]), u2h2(P1[5])),
                                 __hadd2(u2h2(P1[6]), u2h2(P1[7])));
            float2 f0 = __half22float2(s0); l0 += f0.x + f0.y;
            float2 f1 = __half22float2(s1); l1 += f1.x + f1.y;
        }

        // ---- PV half B (m = 2,3) ----
        #pragma unroll
        for (int m = 2; m < 4; m++) {
            uint32_t a[4] = { P0[2*m], P1[2*m], P0[2*m+1], P1[2*m+1] };
            #pragma unroll
            for (int dn = 0; dn < 8; dn++) {
                const __half* vb = Vb + (dn * 8 + g) * KVS + m * 16 + 2 * t;
                uint32_t b0 = *(const uint32_t*)(vb);
                uint32_t b1 = *(const uint32_t*)(vb + 8);
                mma_f16h(O0[dn], O1[dn], a, b0, b1);
            }
        }

        __syncthreads();
        if (it + 2 < 16) {
            const int nj = jt + 128, buf = it & 1;
            cpa16(&Ks[buf][cr0 * KVS + cc0], kg + (size_t)(nj + cr0) * 256 + cc0);
            cpa16(&Ks[buf][cr1 * KVS + cc1], kg + (size_t)(nj + cr1) * 256 + cc1);
            cpa16(&Vt[buf][cr0 * KVS + cc0], vg + (size_t)cr0 * 1024 + nj + cc0);
            cpa16(&Vt[buf][cr1 * KVS + cc1], vg + (size_t)cr1 * 1024 + nj + cc1);
        }
        CP_COMMIT();
    }

    // ---- epilogue: reduce l across t-group, normalize, store fp16 ----
    l0 += __shfl_xor_sync(0xffffffffu, l0, 1);
    l0 += __shfl_xor_sync(0xffffffffu, l0, 2);
    l1 += __shfl_xor_sync(0xffffffffu, l1, 1);
    l1 += __shfl_xor_sync(0xffffffffu, l1, 2);
    const float inv0 = 1.f / l0, inv1 = 1.f / l1;
    __half* ob = g_aoh + ((size_t)(b * Sn + s0 + w * 16)) * 256 + h * 64;
    #pragma unroll
    for (int nt = 0; nt < 8; nt++) {
        const int n = nt * 8 + 2 * t;
        float2 f0 = __half22float2(u2h2(O0[nt]));
        float2 f1 = __half22float2(u2h2(O1[nt]));
        *reinterpret_cast<__half2*>(&ob[(size_t) g      * 256 + n]) =
            __floats2half2_rn(f0.x * inv0, f0.y * inv0);
        *reinterpret_cast<__half2*>(&ob[(size_t)(g + 8) * 256 + n]) =
            __floats2half2_rn(f1.x * inv1, f1.y * inv1);
    }
}

// ---------------------------------------------------------------------------
// Output projection + reshape-scatter + residual (fp16 GEMM, fp32 epilogue)
// ---------------------------------------------------------------------------
__global__ void __launch_bounds__(256) oproj_kernel(const float* __restrict__ x,
                                                    const float* __restrict__ bo,
                                                    float* __restrict__ out)
{
    __shared__ __align__(16) __half As[2][128 * ASTR];
    __shared__ __align__(16) __half Bs[2][64 * BSTR];
    const int tid = threadIdx.x;
    const int w = tid >> 5, lane = tid & 31, g = lane >> 2, t = lane & 3;
    const int wm = w >> 1, wn = w & 1;
    const int m0 = blockIdx.y * 128, n0 = blockIdx.x * 64;
    const __half* Ag = g_aoh + (size_t)m0 * 256;
    const __half* Bg = g_wot + (size_t)n0 * 256;

    const int ar0 = tid >> 2,         ac0 = (tid & 3) * 8;
    const int ar1 = (tid + 256) >> 2, ac1 = ac0;
    const int br  = tid >> 2,         bc  = (tid & 3) * 8;

    #pragma unroll
    for (int pc = 0; pc < 2; pc++) {
        cpa16(&As[pc][ar0 * ASTR + ac0], Ag + (size_t)ar0 * 256 + pc * 32 + ac0);
        cpa16(&As[pc][ar1 * ASTR + ac1], Ag + (size_t)ar1 * 256 + pc * 32 + ac1);
        cpa16(&Bs[pc][br * BSTR + bc],   Bg + (size_t)br * 256 + pc * 32 + bc);
        CP_COMMIT();
    }

    float acc[2][4][4] = {};
    for (int kc = 0; kc < 8; kc++) {
        CP_WAIT1();
        __syncthreads();
        const __half* Ab = As[kc & 1];
        const __half* Bb = Bs[kc & 1];
        #pragma unroll
        for (int ks = 0; ks < 2; ks++) {
            uint32_t a[2][4], bb[4][2];
            #pragma unroll
            for (int mt = 0; mt < 2; mt++) {
                const int r = wm * 32 + mt * 16 + g;
                a[mt][0] = *(const uint32_t*)(Ab + (r    ) * ASTR + ks * 16 + 2 * t);
                a[mt][1] = *(const uint32_t*)(Ab + (r + 8) * ASTR + ks * 16 + 2 * t);
                a[mt][2] = *(const uint32_t*)(Ab + (r    ) * ASTR + ks * 16 + 2 * t + 8);
                a[mt][3] = *(const uint32_t*)(Ab + (r + 8) * ASTR + ks * 16 + 2 * t + 8);
            }
            #pragma unroll
            for (int nt = 0; nt < 4; nt++) {
                const int r = wn * 32 + nt * 8 + g;
                bb[nt][0] = *(const uint32_t*)(Bb + r * BSTR + ks * 16 + 2 * t);
                bb[nt][1] = *(const uint32_t*)(Bb + r * BSTR + ks * 16 + 2 * t + 8);
            }
            #pragma unroll
            for (int mt = 0; mt < 2; mt++)
                #pragma unroll
                for (int nt = 0; nt < 4; nt++)
                    mma_f16(acc[mt][nt], a[mt], bb[nt][0], bb[nt][1]);
        }
        __syncthreads();
        if (kc + 2 < 8) {
            const int nk = kc + 2, buf = kc & 1;
            cpa16(&As[buf][ar0 * ASTR + ac0], Ag + (size_t)ar0 * 256 + nk * 32 + ac0);
            cpa16(&As[buf][ar1 * ASTR + ac1], Ag + (size_t)ar1 * 256 + nk * 32 + ac1);
            cpa16(&Bs[buf][br * BSTR + bc],   Bg + (size_t)br * 256 + nk * 32 + bc);
        }
        CP_COMMIT();
    }

    #pragma unroll
    for (int mt = 0; mt < 2; mt++) {
        const int row0 = m0 + wm * 32 + mt * 16 + g;
        #pragma unroll
        for (int nt = 0; nt < 4; nt++) {
            const int n = n0 + wn * 32 + nt * 8 + 2 * t;
            const float2 bb = *reinterpret_cast<const float2*>(&bo[n]);
            #pragma unroll
            for (int rr = 0; rr < 2; rr++) {
                const int m  = row0 + rr * 8;
                const int bv = m >> 10;
                const int hw = m & 1023;
                const size_t flat = ((size_t)(bv * 256 + (hw >> 2))) * 1024
                                  + (size_t)(hw & 3) * 256 + n;
                const float2 xr = *reinterpret_cast<const float2*>(&x[flat]);
                float2 o;
                o.x = acc[mt][nt][2*rr]   + bb.x + xr.x;
                o.y = acc[mt][nt][2*rr+1] + bb.y + xr.y;
                *reinterpret_cast<float2*>(&out[flat]) = o;
            }
        }
    }
}

// ---------------------------------------------------------------------------
extern "C" void kernel_launch(void* const* d_in, const int* in_sizes, int n_in,
                              void* d_out, int out_size)
{
    const float* x  = (const float*)d_in[0];
    const float* Wq = (const float*)d_in[1];
    const float* bq = (const float*)d_in[2];
    const float* Wk = (const float*)d_in[3];
    const float* bk = (const float*)d_in[4];
    const float* Wv = (const float*)d_in[5];
    const float* bv = (const float*)d_in[6];
    const float* Wo = (const float*)d_in[7];
    const float* bo = (const float*)d_in[8];
    float* out = (float*)d_out;

    prep_all<<<7680, dim3(32, 8)>>>(x, Wq, Wk, Wv, Wo);
    qkvproj_kernel<<<896, 256>>>(bq, bk, bv);
    attn_kernel  <<<dim3(48, 4, 4), 256>>>();
    oproj_kernel <<<dim3(4, 192), 256>>>(x, bo, out);
}

// round 15
// speedup vs baseline: 1.0631x; 1.0250x over previous
#include <cuda_runtime.h>
#include <cuda_fp16.h>
#include <cstdint>

// Problem constants
#define Bn   4
#define Vn   6
#define Cn   256
#define HWn  1024
#define Sn   6144
#define WIN  3
#define QSCALE (0.125f * 1.44269504f)   // 1/sqrt(64) * log2(e)

// Scratch (__device__ globals; allocation-free rule)
__device__ __half g_xt [(size_t)Bn * Vn * HWn * Cn];  // [bv][hw][c]
__device__ __half g_qh [(size_t)Bn * Sn  * Cn];       // [B,S,C]  (scaled by QSCALE)
__device__ __half g_kh [(size_t)Bn * HWn * Cn];       // [B,HW,C]
__device__ __half g_vt [(size_t)Bn * Cn  * HWn];      // [B,C,HW] (transposed)
__device__ __half g_aoh[(size_t)Bn * Sn  * Cn];       // [B,S,C]
__device__ __half g_wqt[256 * 256];                   // W^T [n][k]
__device__ __half g_wkt[256 * 1536];
__device__ __half g_wvt[256 * 1536];
__device__ __half g_wot[256 * 256];

// ---------------------------------------------------------------------------
// helpers
// ---------------------------------------------------------------------------
__device__ __forceinline__ void mma_f16(float* d, const uint32_t* a,
                                        uint32_t b0, uint32_t b1)
{
    asm volatile(
        "mma.sync.aligned.m16n8k16.row.col.f32.f16.f16.f32 "
        "{%0,%1,%2,%3}, {%4,%5,%6,%7}, {%8,%9}, {%0,%1,%2,%3};"
        : "+f"(d[0]), "+f"(d[1]), "+f"(d[2]), "+f"(d[3])
        : "r"(a[0]), "r"(a[1]), "r"(a[2]), "r"(a[3]), "r"(b0), "r"(b1));
}

// fp16-accumulator mma: D,C are 2 regs (4 halves).
__device__ __forceinline__ void mma_f16h(uint32_t& d0, uint32_t& d1,
                                         const uint32_t* a,
                                         uint32_t b0, uint32_t b1)
{
    asm volatile(
        "mma.sync.aligned.m16n8k16.row.col.f16.f16.f16.f16 "
        "{%0,%1}, {%2,%3,%4,%5}, {%6,%7}, {%0,%1};"
        : "+r"(d0), "+r"(d1)
        : "r"(a[0]), "r"(a[1]), "r"(a[2]), "r"(a[3]), "r"(b0), "r"(b1));
}

__device__ __forceinline__ void ldsm_x4(uint32_t& r0, uint32_t& r1,
                                        uint32_t& r2, uint32_t& r3, uint32_t addr)
{
    asm volatile("ldmatrix.sync.aligned.m8n8.x4.shared.b16 {%0,%1,%2,%3}, [%4];"
                 : "=r"(r0), "=r"(r1), "=r"(r2), "=r"(r3) : "r"(addr));
}

__device__ __forceinline__ uint32_t h2exp2u(uint32_t x)
{
    __half2 h = h2exp2(*reinterpret_cast<__half2*>(&x));
    return *reinterpret_cast<uint32_t*>(&h);
}

__device__ __forceinline__ __half2 u2h2(uint32_t x)
{
    return *reinterpret_cast<__half2*>(&x);
}

__device__ __forceinline__ void cpa16(__half* dst, const __half* src)
{
    uint32_t s = (uint32_t)__cvta_generic_to_shared(dst);
    asm volatile("cp.async.cg.shared.global [%0], [%1], 16;" :: "r"(s), "l"(src));
}
#define CP_COMMIT() asm volatile("cp.async.commit_group;")
#define CP_WAIT1()  asm volatile("cp.async.wait_group 1;")

#define ASTR 40     // halves per A smem row (32 k + 8 pad)
#define BSTR 40
#define KVS  72     // halves per KV smem row (64 + 8 pad)
#define HNINF 0xFC00u   // fp16 -inf bits

// ---------------------------------------------------------------------------
// prep (merged): blocks [0,6144) transpose x -> fp16 [bv][hw][c];
// blocks [6144,7680) transpose weights W [K][256] -> W^T fp16 [256][K].
// ---------------------------------------------------------------------------
__global__ void prep_all(const float* __restrict__ x,
                         const float* __restrict__ Wq, const float* __restrict__ Wk,
                         const float* __restrict__ Wv, const float* __restrict__ Wo)
{
    __shared__ float ts[32][33];
    const int tx = threadIdx.x, ty = threadIdx.y;
    const int idx = blockIdx.x;
    if (idx < 6144) {
        const int hw0 = (idx & 31) * 32;
        const int c0  = ((idx >> 5) & 7) * 32;
        const int bv  = idx >> 8;
        #pragma unroll
        for (int r = 0; r < 4; r++) {
            const int c = c0 + ty * 4 + r;
            ts[ty * 4 + r][tx] = x[((size_t)bv * 256 + c) * 1024 + hw0 + tx];
        }
        __syncthreads();
        #pragma unroll
        for (int r = 0; r < 4; r++) {
            const int hw = hw0 + ty * 4 + r;
            g_xt[((size_t)bv * 1024 + hw) * 256 + c0 + tx] =
                __float2half(ts[tx][ty * 4 + r]);
        }
    } else {
        const int j  = idx - 6144;
        const int n0 = (j & 7) * 32;
        const int k0 = ((j >> 3) % 48) * 32;
        const int ws = j / 384;
        const float* src; __half* dst; int K;
        switch (ws) {
            case 0:  src = Wq; dst = g_wqt; K = 256;  break;
            case 1:  src = Wk; dst = g_wkt; K = 1536; break;
            case 2:  src = Wv; dst = g_wvt; K = 1536; break;
            default: src = Wo; dst = g_wot; K = 256;  break;
        }
        if (k0 >= K) return;
        #pragma unroll
        for (int r = 0; r < 4; r++)
            ts[ty * 4 + r][tx] = src[(size_t)(k0 + ty * 4 + r) * 256 + n0 + tx];
        __syncthreads();
        #pragma unroll
        for (int r = 0; r < 4; r++)
            dst[(size_t)(n0 + ty * 4 + r) * K + k0 + tx] =
                __float2half(ts[tx][ty * 4 + r]);
    }
}

// ---------------------------------------------------------------------------
// Fused Q + KV projection launch (unchanged, best config).
// ---------------------------------------------------------------------------
__device__ __forceinline__ void qproj_body(__half* sbuf, int bx, int by,
                                           const float* __restrict__ bq)
{
    __half* As = sbuf;
    __half* Bs = sbuf + 2 * 128 * ASTR;
    const int tid = threadIdx.x;
    const int w = tid >> 5, lane = tid & 31, g = lane >> 2, t = lane & 3;
    const int wm = w >> 1, wn = w & 1;
    const int m0 = by * 128, n0 = bx * 64;
    const __half* Ag = g_xt + (size_t)m0 * 256;
    const __half* Bg = g_wqt + (size_t)n0 * 256;

    const int ar0 = tid >> 2,           ac0 = (tid & 3) * 8;
    const int ar1 = (tid + 256) >> 2,   ac1 = ac0;
    const int br  = tid >> 2,           bc  = (tid & 3) * 8;

    #pragma unroll
    for (int pc = 0; pc < 2; pc++) {
        __half* Asb = As + pc * 128 * ASTR;
        __half* Bsb = Bs + pc * 64 * BSTR;
        cpa16(&Asb[ar0 * ASTR + ac0], Ag + (size_t)ar0 * 256 + pc * 32 + ac0);
        cpa16(&Asb[ar1 * ASTR + ac1], Ag + (size_t)ar1 * 256 + pc * 32 + ac1);
        cpa16(&Bsb[br * BSTR + bc],   Bg + (size_t)br * 256 + pc * 32 + bc);
        CP_COMMIT();
    }

    float acc[2][4][4] = {};
    for (int kc = 0; kc < 8; kc++) {
        CP_WAIT1();
        __syncthreads();
        const __half* Ab = As + (kc & 1) * 128 * ASTR;
        const __half* Bb = Bs + (kc & 1) * 64 * BSTR;
        #pragma unroll
        for (int ks = 0; ks < 2; ks++) {
            uint32_t a[2][4], bb[4][2];
            #pragma unroll
            for (int mt = 0; mt < 2; mt++) {
                const int r = wm * 32 + mt * 16 + g;
                a[mt][0] = *(const uint32_t*)(Ab + (r    ) * ASTR + ks * 16 + 2 * t);
                a[mt][1] = *(const uint32_t*)(Ab + (r + 8) * ASTR + ks * 16 + 2 * t);
                a[mt][2] = *(const uint32_t*)(Ab + (r    ) * ASTR + ks * 16 + 2 * t + 8);
                a[mt][3] = *(const uint32_t*)(Ab + (r + 8) * ASTR + ks * 16 + 2 * t + 8);
            }
            #pragma unroll
            for (int nt = 0; nt < 4; nt++) {
                const int r = wn * 32 + nt * 8 + g;
                bb[nt][0] = *(const uint32_t*)(Bb + r * BSTR + ks * 16 + 2 * t);
                bb[nt][1] = *(const uint32_t*)(Bb + r * BSTR + ks * 16 + 2 * t + 8);
            }
            #pragma unroll
            for (int mt = 0; mt < 2; mt++)
                #pragma unroll
                for (int nt = 0; nt < 4; nt++)
                    mma_f16(acc[mt][nt], a[mt], bb[nt][0], bb[nt][1]);
        }
        __syncthreads();
        if (kc + 2 < 8) {
            const int nk = (kc + 2) * 32;
            __half* Asb = As + (kc & 1) * 128 * ASTR;
            __half* Bsb = Bs + (kc & 1) * 64 * BSTR;
            cpa16(&Asb[ar0 * ASTR + ac0], Ag + (size_t)ar0 * 256 + nk + ac0);
            cpa16(&Asb[ar1 * ASTR + ac1], Ag + (size_t)ar1 * 256 + nk + ac1);
            cpa16(&Bsb[br * BSTR + bc],   Bg + (size_t)br * 256 + nk + bc);
        }
        CP_COMMIT();
    }

    #pragma unroll
    for (int mt = 0; mt < 2; mt++) {
        const int row0 = m0 + wm * 32 + mt * 16 + g;
        #pragma unroll
        for (int nt = 0; nt < 4; nt++) {
            const int n = n0 + wn * 32 + nt * 8 + 2 * t;
            const float2 bb = *reinterpret_cast<const float2*>(&bq[n]);
            __half2 h0 = __floats2half2_rn((acc[mt][nt][0] + bb.x) * QSCALE,
                                           (acc[mt][nt][1] + bb.y) * QSCALE);
            __half2 h1 = __floats2half2_rn((acc[mt][nt][2] + bb.x) * QSCALE,
                                           (acc[mt][nt][3] + bb.y) * QSCALE);
            *reinterpret_cast<__half2*>(&g_qh[(size_t) row0      * 256 + n]) = h0;
            *reinterpret_cast<__half2*>(&g_qh[(size_t)(row0 + 8) * 256 + n]) = h1;
        }
    }
}

__device__ __forceinline__ void kvproj_body(__half* sbuf, int bx, int by,
                                            const float* __restrict__ bk,
                                            const float* __restrict__ bv)
{
    __half* As  = sbuf;
    __half* Bks = sbuf + 2 * 128 * ASTR;
    __half* Bvs = Bks + 2 * 64 * BSTR;
    const int tid = threadIdx.x;
    const int w = tid >> 5, lane = tid & 31, g = lane >> 2, t = lane & 3;
    const int wm = w >> 1, wn = w & 1;
    const int m0 = by * 128, n0 = bx * 64;
    const int bidx = m0 >> 10, hw0 = m0 & 1023;

    const int ar0 = tid >> 2,         ac0 = (tid & 3) * 8;
    const int ar1 = (tid + 256) >> 2, ac1 = ac0;
    const int br  = tid >> 2,         bc  = (tid & 3) * 8;

    #pragma unroll
    for (int pc = 0; pc < 2; pc++) {
        const int k0 = pc * 32, v = k0 >> 8, c0 = k0 & 255;
        const __half* Ag = g_xt + ((size_t)(bidx * Vn + v) * 1024 + hw0) * 256 + c0;
        __half* Asb  = As  + pc * 128 * ASTR;
        __half* Bksb = Bks + pc * 64 * BSTR;
        __half* Bvsb = Bvs + pc * 64 * BSTR;
        cpa16(&Asb[ar0 * ASTR + ac0], Ag + (size_t)ar0 * 256 + ac0);
        cpa16(&Asb[ar1 * ASTR + ac1], Ag + (size_t)ar1 * 256 + ac1);
        cpa16(&Bksb[br * BSTR + bc], g_wkt + (size_t)(n0 + br) * 1536 + k0 + bc);
        cpa16(&Bvsb[br * BSTR + bc], g_wvt + (size_t)(n0 + br) * 1536 + k0 + bc);
        CP_COMMIT();
    }

    float acck[2][4][4] = {};
    float accv[2][4][4] = {};
    for (int kc = 0; kc < 48; kc++) {
        CP_WAIT1();
        __syncthreads();
        const __half* Ab  = As  + (kc & 1) * 128 * ASTR;
        const __half* Bkb = Bks + (kc & 1) * 64 * BSTR;
        const __half* Bvb = Bvs + (kc & 1) * 64 * BSTR;
        #pragma unroll
        for (int ks = 0; ks < 2; ks++) {
            uint32_t a[2][4], bkf[4][2], bvf[4][2];
            #pragma unroll
            for (int mt = 0; mt < 2; mt++) {
                const int r = wm * 32 + mt * 16 + g;
                a[mt][0] = *(const uint32_t*)(Ab + (r    ) * ASTR + ks * 16 + 2 * t);
                a[mt][1] = *(const uint32_t*)(Ab + (r + 8) * ASTR + ks * 16 + 2 * t);
                a[mt][2] = *(const uint32_t*)(Ab + (r    ) * ASTR + ks * 16 + 2 * t + 8);
                a[mt][3] = *(const uint32_t*)(Ab + (r + 8) * ASTR + ks * 16 + 2 * t + 8);
            }
            #pragma unroll
            for (int nt = 0; nt < 4; nt++) {
                const int r = wn * 32 + nt * 8 + g;
                bkf[nt][0] = *(const uint32_t*)(Bkb + r * BSTR + ks * 16 + 2 * t);
                bkf[nt][1] = *(const uint32_t*)(Bkb + r * BSTR + ks * 16 + 2 * t + 8);
                bvf[nt][0] = *(const uint32_t*)(Bvb + r * BSTR + ks * 16 + 2 * t);
                bvf[nt][1] = *(const uint32_t*)(Bvb + r * BSTR + ks * 16 + 2 * t + 8);
            }
            #pragma unroll
            for (int mt = 0; mt < 2; mt++)
                #pragma unroll
                for (int nt = 0; nt < 4; nt++) {
                    mma_f16(acck[mt][nt], a[mt], bkf[nt][0], bkf[nt][1]);
                    mma_f16(accv[mt][nt], a[mt], bvf[nt][0], bvf[nt][1]);
                }
        }
        __syncthreads();
        if (kc + 2 < 48) {
            const int k0 = (kc + 2) * 32, v = k0 >> 8, c0 = k0 & 255;
            const __half* Ag = g_xt + ((size_t)(bidx * Vn + v) * 1024 + hw0) * 256 + c0;
            __half* Asb  = As  + (kc & 1) * 128 * ASTR;
            __half* Bksb = Bks + (kc & 1) * 64 * BSTR;
            __half* Bvsb = Bvs + (kc & 1) * 64 * BSTR;
            cpa16(&Asb[ar0 * ASTR + ac0], Ag + (size_t)ar0 * 256 + ac0);
            cpa16(&Asb[ar1 * ASTR + ac1], Ag + (size_t)ar1 * 256 + ac1);
            cpa16(&Bksb[br * BSTR + bc], g_wkt + (size_t)(n0 + br) * 1536 + k0 + bc);
            cpa16(&Bvsb[br * BSTR + bc], g_wvt + (size_t)(n0 + br) * 1536 + k0 + bc);
        }
        CP_COMMIT();
    }

    #pragma unroll
    for (int mt = 0; mt < 2; mt++) {
        const int row0 = m0 + wm * 32 + mt * 16 + g;
        #pragma unroll
        for (int nt = 0; nt < 4; nt++) {
            const int n = n0 + wn * 32 + nt * 8 + 2 * t;
            const float2 bbk = *reinterpret_cast<const float2*>(&bk[n]);
            const float2 bbv = *reinterpret_cast<const float2*>(&bv[n]);
            #pragma unroll
            for (int rr = 0; rr < 2; rr++) {
                const int r  = row0 + rr * 8;
                const int hw = r & 1023, bb = r >> 10;
                __half2 kh = __floats2half2_rn(acck[mt][nt][2*rr]   + bbk.x,
                                               acck[mt][nt][2*rr+1] + bbk.y);
                *reinterpret_cast<__half2*>(
                    &g_kh[((size_t)(bb * 1024 + hw)) * 256 + n]) = kh;
                g_vt[(((size_t)(bb * 256 + n    )) << 10) + hw] =
                    __float2half(accv[mt][nt][2*rr]   + bbv.x);
                g_vt[(((size_t)(bb * 256 + n + 1)) << 10) + hw] =
                    __float2half(accv[mt][nt][2*rr+1] + bbv.y);
            }
        }
    }
}

__global__ void __launch_bounds__(256) qkvproj_kernel(const float* __restrict__ bq,
                                                      const float* __restrict__ bk,
                                                      const float* __restrict__ bv)
{
    __shared__ __align__(16) __half sbuf[2 * 128 * ASTR + 4 * 64 * BSTR];
    const int idx = blockIdx.x;
    if (idx < 128) {
        kvproj_body(sbuf, idx & 3, idx >> 2, bk, bv);
    } else {
        const int j = idx - 128;
        qproj_body(sbuf, j & 3, j >> 2, bq);
    }
}

// ---------------------------------------------------------------------------
// Flash attention: fp16-acc mma + software-pipelined tile body + LDSM
// fragment loads (24 ldmatrix.x4 replace 128 LDS.32 per tile per warp).
// Phases: QK_A -> exp2_A -> QK_B -> PV_A -> exp2_B -> PV_B.
// CTA = 128 queries (8 warps x m16); 16 key-tiles of 64; 2-stage cp.async.
// ---------------------------------------------------------------------------
__global__ void __launch_bounds__(256) attn_kernel()
{
    __shared__ __align__(16) __half Ks[2][64 * KVS];   // [key][dim]
    __shared__ __align__(16) __half Vt[2][64 * KVS];   // [dim][key]

    const int b  = blockIdx.z;
    const int h  = blockIdx.y;
    const int s0 = blockIdx.x * 128;
    const int tid = threadIdx.x;
    const int w = tid >> 5, lane = tid & 31, g = lane >> 2, t = lane & 3;

    const __half* kg = g_kh + (size_t)b * HWn * 256 + h * 64;          // stride 256
    const __half* vg = g_vt + (((size_t)(b * 256 + h * 64)) << 10);    // stride 1024

    const int cr0 = tid >> 3,         cc0 = (tid & 7) * 8;
    const int cr1 = (tid + 256) >> 3, cc1 = cc0;

    #pragma unroll
    for (int pc = 0; pc < 2; pc++) {
        const int jt = pc * 64;
        cpa16(&Ks[pc][cr0 * KVS + cc0], kg + (size_t)(jt + cr0) * 256 + cc0);
        cpa16(&Ks[pc][cr1 * KVS + cc1], kg + (size_t)(jt + cr1) * 256 + cc1);
        cpa16(&Vt[pc][cr0 * KVS + cc0], vg + (size_t)cr0 * 1024 + jt + cc0);
        cpa16(&Vt[pc][cr1 * KVS + cc1], vg + (size_t)cr1 * 1024 + jt + cc1);
        CP_COMMIT();
    }

    // ldmatrix lane geometry: row within 8x8 = lane&7, matrix id = lane>>3
    const int lr = lane & 7, lj = lane >> 3;
    uint32_t ks_lb[2], vt_lb[2];
    #pragma unroll
    for (int bb2 = 0; bb2 < 2; bb2++) {
        ks_lb[bb2] = (uint32_t)__cvta_generic_to_shared(&Ks[bb2][0])
                   + (uint32_t)((lr * KVS + lj * 8) * 2);
        vt_lb[bb2] = (uint32_t)__cvta_generic_to_shared(&Vt[bb2][0])
                   + (uint32_t)((lr * KVS + lj * 8) * 2);
    }

    // Q fragments (already scaled by QSCALE in qproj)
    const __half* qbase = g_qh + ((size_t)(b * Sn + s0 + w * 16)) * 256 + h * 64;
    uint32_t Qfr[4][4];
    #pragma unroll
    for (int ks = 0; ks < 4; ks++) {
        const int d0 = ks * 16 + 2 * t;
        Qfr[ks][0] = *(const uint32_t*)(qbase + (size_t) g      * 256 + d0);
        Qfr[ks][1] = *(const uint32_t*)(qbase + (size_t)(g + 8) * 256 + d0);
        Qfr[ks][2] = *(const uint32_t*)(qbase + (size_t) g      * 256 + d0 + 8);
        Qfr[ks][3] = *(const uint32_t*)(qbase + (size_t)(g + 8) * 256 + d0 + 8);
    }

    uint32_t O0[8], O1[8];
    #pragma unroll
    for (int i = 0; i < 8; i++) { O0[i] = 0u; O1[i] = 0u; }
    float l0 = 0.f, l1 = 0.f;
    const int r0 = s0 + w * 16 + g, r1 = r0 + 8;

    for (int it = 0; it < 16; it++) {
        const int jt = it * 64;
        CP_WAIT1();
        __syncthreads();
        const uint32_t kbase = ks_lb[it & 1];
        const uint32_t vbase = vt_lb[it & 1];
        const bool masked = (jt <= s0 + 130) && (jt + 66 >= s0);

        uint32_t P0[8], P1[8];

        // ---- QK half A (nt 0..3) via LDSM ----
        #pragma unroll
        for (int nt = 0; nt < 4; nt++) {
            P0[nt] = 0u; P1[nt] = 0u;
            const uint32_t rowb = kbase + (uint32_t)(nt * 8 * KVS * 2);
            uint32_t kb[8];
            ldsm_x4(kb[0], kb[1], kb[2], kb[3], rowb);       // dims 0..31
            ldsm_x4(kb[4], kb[5], kb[6], kb[7], rowb + 64);  // dims 32..63
            #pragma unroll
            for (int ks = 0; ks < 4; ks++)
                mma_f16h(P0[nt], P1[nt], Qfr[ks], kb[ks * 2], kb[ks * 2 + 1]);
        }

        // ---- mask + exp2 + l for half A ----
        if (masked) {
            #pragma unroll
            for (int nt = 0; nt < 4; nt++) {
                const int c = jt + nt * 8 + 2 * t;
                uint32_t m0 = 0u, m1 = 0u;
                if ((unsigned)(c     - r0 + WIN) <= 2u * WIN) m0 |= HNINF;
                if ((unsigned)(c + 1 - r0 + WIN) <= 2u * WIN) m0 |= HNINF << 16;
                if ((unsigned)(c     - r1 + WIN) <= 2u * WIN) m1 |= HNINF;
                if ((unsigned)(c + 1 - r1 + WIN) <= 2u * WIN) m1 |= HNINF << 16;
                if (m0) { __half2 s = __hadd2(u2h2(P0[nt]), u2h2(m0));
                          P0[nt] = *reinterpret_cast<uint32_t*>(&s); }
                if (m1) { __half2 s = __hadd2(u2h2(P1[nt]), u2h2(m1));
                          P1[nt] = *reinterpret_cast<uint32_t*>(&s); }
            }
        }
        #pragma unroll
        for (int nt = 0; nt < 4; nt++) {
            P0[nt] = h2exp2u(P0[nt]);
            P1[nt] = h2exp2u(P1[nt]);
        }
        {
            __half2 s0 = __hadd2(__hadd2(u2h2(P0[0]), u2h2(P0[1])),
                                 __hadd2(u2h2(P0[2]), u2h2(P0[3])));
            __half2 s1 = __hadd2(__hadd2(u2h2(P1[0]), u2h2(P1[1])),
                                 __hadd2(u2h2(P1[2]), u2h2(P1[3])));
            float2 f0 = __half22float2(s0); l0 += f0.x + f0.y;
            float2 f1 = __half22float2(s1); l1 += f1.x + f1.y;
        }

        // ---- QK half B (nt 4..7) via LDSM — overlaps exp2_A latency ----
        #pragma unroll
        for (int nt = 4; nt < 8; nt++) {
            P0[nt] = 0u; P1[nt] = 0u;
            const uint32_t rowb = kbase + (uint32_t)(nt * 8 * KVS * 2);
            uint32_t kb[8];
            ldsm_x4(kb[0], kb[1], kb[2], kb[3], rowb);
            ldsm_x4(kb[4], kb[5], kb[6], kb[7], rowb + 64);
            #pragma unroll
            for (int ks = 0; ks < 4; ks++)
                mma_f16h(P0[nt], P1[nt], Qfr[ks], kb[ks * 2], kb[ks * 2 + 1]);
        }

        // ---- PV half A (m = 0,1; keys 0..31) via LDSM ----
        #pragma unroll
        for (int dn = 0; dn < 8; dn++) {
            const uint32_t rowb = vbase + (uint32_t)(dn * 8 * KVS * 2);
            uint32_t vb[4];
            ldsm_x4(vb[0], vb[1], vb[2], vb[3], rowb);       // keys 0..31
            uint32_t a0[4] = { P0[0], P1[0], P0[1], P1[1] };
            uint32_t a1[4] = { P0[2], P1[2], P0[3], P1[3] };
            mma_f16h(O0[dn], O1[dn], a0, vb[0], vb[1]);
            mma_f16h(O0[dn], O1[dn], a1, vb[2], vb[3]);
        }

        // ---- mask + exp2 + l for half B — overlaps PV_A issue ----
        if (masked) {
            #pragma unroll
            for (int nt = 4; nt < 8; nt++) {
                const int c = jt + nt * 8 + 2 * t;
                uint32_t m0 = 0u, m1 = 0u;
                if ((unsigned)(c     - r0 + WIN) <= 2u * WIN) m0 |= HNINF;
                if ((unsigned)(c + 1 - r0 + WIN) <= 2u * WIN) m0 |= HNINF << 16;
                if ((unsigned)(c     - r1 + WIN) <= 2u * WIN) m1 |= HNINF;
                if ((unsigned)(c + 1 - r1 + WIN) <= 2u * WIN) m1 |= HNINF << 16;
                if (m0) { __half2 s = __hadd2(u2h2(P0[nt]), u2h2(m0));
                          P0[nt] = *reinterpret_cast<uint32_t*>(&s); }
                if (m1) { __half2 s = __hadd2(u2h2(P1[nt]), u2h2(m1));
                          P1[nt] = *reinterpret_cast<uint32_t*>(&s); }
            }
        }
        #pragma unroll
        for (int nt = 4; nt < 8; nt++) {
            P0[nt] = h2exp2u(P0[nt]);
            P1[nt] = h2exp2u(P1[nt]);
        }
        {
            __half2 s0 = __hadd2(__hadd2(u2h2(P0[4]), u2h2(P0[5])),
                                 __hadd2(u2h2(P0[6]), u2h2(P0[7])));
            __half2 s1 = __hadd2(__hadd2(u2h2(P1[4]), u2h2(P1[5])),
                                 __hadd2(u2h2(P1[6]), u2h2(P1[7])));
            float2 f0 = __half22float2(s0); l0 += f0.x + f0.y;
            float2 f1 = __half22float2(s1); l1 += f1.x + f1.y;
        }

        // ---- PV half B (m = 2,3; keys 32..63) via LDSM ----
        #pragma unroll
        for (int dn = 0; dn < 8; dn++) {
            const uint32_t rowb = vbase + (uint32_t)(dn * 8 * KVS * 2);
            uint32_t vb[4];
            ldsm_x4(vb[0], vb[1], vb[2], vb[3], rowb + 64);  // keys 32..63
            uint32_t a0[4] = { P0[4], P1[4], P0[5], P1[5] };
            uint32_t a1[4] = { P0[6], P1[6], P0[7], P1[7] };
            mma_f16h(O0[dn], O1[dn], a0, vb[0], vb[1]);
            mma_f16h(O0[dn], O1[dn], a1, vb[2], vb[3]);
        }

        __syncthreads();
        if (it + 2 < 16) {
            const int nj = jt + 128, buf = it & 1;
            cpa16(&Ks[buf][cr0 * KVS + cc0], kg + (size_t)(nj + cr0) * 256 + cc0);
            cpa16(&Ks[buf][cr1 * KVS + cc1], kg + (size_t)(nj + cr1) * 256 + cc1);
            cpa16(&Vt[buf][cr0 * KVS + cc0], vg + (size_t)cr0 * 1024 + nj + cc0);
            cpa16(&Vt[buf][cr1 * KVS + cc1], vg + (size_t)cr1 * 1024 + nj + cc1);
        }
        CP_COMMIT();
    }

    // ---- epilogue: reduce l across t-group, normalize, store fp16 ----
    l0 += __shfl_xor_sync(0xffffffffu, l0, 1);
    l0 += __shfl_xor_sync(0xffffffffu, l0, 2);
    l1 += __shfl_xor_sync(0xffffffffu, l1, 1);
    l1 += __shfl_xor_sync(0xffffffffu, l1, 2);
    const float inv0 = 1.f / l0, inv1 = 1.f / l1;
    __half* ob = g_aoh + ((size_t)(b * Sn + s0 + w * 16)) * 256 + h * 64;
    #pragma unroll
    for (int nt = 0; nt < 8; nt++) {
        const int n = nt * 8 + 2 * t;
        float2 f0 = __half22float2(u2h2(O0[nt]));
        float2 f1 = __half22float2(u2h2(O1[nt]));
        *reinterpret_cast<__half2*>(&ob[(size_t) g      * 256 + n]) =
            __floats2half2_rn(f0.x * inv0, f0.y * inv0);
        *reinterpret_cast<__half2*>(&ob[(size_t)(g + 8) * 256 + n]) =
            __floats2half2_rn(f1.x * inv1, f1.y * inv1);
    }
}

// ---------------------------------------------------------------------------
// Output projection + reshape-scatter + residual (fp16 GEMM, fp32 epilogue)
// ---------------------------------------------------------------------------
__global__ void __launch_bounds__(256) oproj_kernel(const float* __restrict__ x,
                                                    const float* __restrict__ bo,
                                                    float* __restrict__ out)
{
    __shared__ __align__(16) __half As[2][128 * ASTR];
    __shared__ __align__(16) __half Bs[2][64 * BSTR];
    const int tid = threadIdx.x;
    const int w = tid >> 5, lane = tid & 31, g = lane >> 2, t = lane & 3;
    const int wm = w >> 1, wn = w & 1;
    const int m0 = blockIdx.y * 128, n0 = blockIdx.x * 64;
    const __half* Ag = g_aoh + (size_t)m0 * 256;
    const __half* Bg = g_wot + (size_t)n0 * 256;

    const int ar0 = tid >> 2,         ac0 = (tid & 3) * 8;
    const int ar1 = (tid + 256) >> 2, ac1 = ac0;
    const int br  = tid >> 2,         bc  = (tid & 3) * 8;

    #pragma unroll
    for (int pc = 0; pc < 2; pc++) {
        cpa16(&As[pc][ar0 * ASTR + ac0], Ag + (size_t)ar0 * 256 + pc * 32 + ac0);
        cpa16(&As[pc][ar1 * ASTR + ac1], Ag + (size_t)ar1 * 256 + pc * 32 + ac1);
        cpa16(&Bs[pc][br * BSTR + bc],   Bg + (size_t)br * 256 + pc * 32 + bc);
        CP_COMMIT();
    }

    float acc[2][4][4] = {};
    for (int kc = 0; kc < 8; kc++) {
        CP_WAIT1();
        __syncthreads();
        const __half* Ab = As[kc & 1];
        const __half* Bb = Bs[kc & 1];
        #pragma unroll
        for (int ks = 0; ks < 2; ks++) {
            uint32_t a[2][4], bb[4][2];
            #pragma unroll
            for (int mt = 0; mt < 2; mt++) {
                const int r = wm * 32 + mt * 16 + g;
                a[mt][0] = *(const uint32_t*)(Ab + (r    ) * ASTR + ks * 16 + 2 * t);
                a[mt][1] = *(const uint32_t*)(Ab + (r + 8) * ASTR + ks * 16 + 2 * t);
                a[mt][2] = *(const uint32_t*)(Ab + (r    ) * ASTR + ks * 16 + 2 * t + 8);
                a[mt][3] = *(const uint32_t*)(Ab + (r + 8) * ASTR + ks * 16 + 2 * t + 8);
            }
            #pragma unroll
            for (int nt = 0; nt < 4; nt++) {
                const int r = wn * 32 + nt * 8 + g;
                bb[nt][0] = *(const uint32_t*)(Bb + r * BSTR + ks * 16 + 2 * t);
                bb[nt][1] = *(const uint32_t*)(Bb + r * BSTR + ks * 16 + 2 * t + 8);
            }
            #pragma unroll
            for (int mt = 0; mt < 2; mt++)
                #pragma unroll
                for (int nt = 0; nt < 4; nt++)
                    mma_f16(acc[mt][nt], a[mt], bb[nt][0], bb[nt][1]);
        }
        __syncthreads();
        if (kc + 2 < 8) {
            const int nk = kc + 2, buf = kc & 1;
            cpa16(&As[buf][ar0 * ASTR + ac0], Ag + (size_t)ar0 * 256 + nk * 32 + ac0);
            cpa16(&As[buf][ar1 * ASTR + ac1], Ag + (size_t)ar1 * 256 + nk * 32 + ac1);
            cpa16(&Bs[buf][br * BSTR + bc],   Bg + (size_t)br * 256 + nk * 32 + bc);
        }
        CP_COMMIT();
    }

    #pragma unroll
    for (int mt = 0; mt < 2; mt++) {
        const int row0 = m0 + wm * 32 + mt * 16 + g;
        #pragma unroll
        for (int nt = 0; nt < 4; nt++) {
            const int n = n0 + wn * 32 + nt * 8 + 2 * t;
            const float2 bb = *reinterpret_cast<const float2*>(&bo[n]);
            #pragma unroll
            for (int rr = 0; rr < 2; rr++) {
                const int m  = row0 + rr * 8;
                const int bv = m >> 10;
                const int hw = m & 1023;
                const size_t flat = ((size_t)(bv * 256 + (hw >> 2))) * 1024
                                  + (size_t)(hw & 3) * 256 + n;
                const float2 xr = *reinterpret_cast<const float2*>(&x[flat]);
                float2 o;
                o.x = acc[mt][nt][2*rr]   + bb.x + xr.x;
                o.y = acc[mt][nt][2*rr+1] + bb.y + xr.y;
                *reinterpret_cast<float2*>(&out[flat]) = o;
            }
        }
    }
}

// ---------------------------------------------------------------------------
extern "C" void kernel_launch(void* const* d_in, const int* in_sizes, int n_in,
                              void* d_out, int out_size)
{
    const float* x  = (const float*)d_in[0];
    const float* Wq = (const float*)d_in[1];
    const float* bq = (const float*)d_in[2];
    const float* Wk = (const float*)d_in[3];
    const float* bk = (const float*)d_in[4];
    const float* Wv = (const float*)d_in[5];
    const float* bv = (const float*)d_in[6];
    const float* Wo = (const float*)d_in[7];
    const float* bo = (const float*)d_in[8];
    float* out = (float*)d_out;

    prep_all<<<7680, dim3(32, 8)>>>(x, Wq, Wk, Wv, Wo);
    qkvproj_kernel<<<896, 256>>>(bq, bk, bv);
    attn_kernel  <<<dim3(48, 4, 4), 256>>>();
    oproj_kernel <<<dim3(4, 192), 256>>>(x, bo, out);
}